// round 14
// baseline (speedup 1.0000x reference)
#include <cuda_runtime.h>
#include <math.h>

#define BB 256
#define TT 64
#define HH 256
#define DD 8

struct GruP {
    const float *Wih0, *Whh0, *bih0, *bhh0;
    const float *Wih1, *Whh1, *bih1, *bhh1;
};

// Persistent state (device globals: allocation-free scratch)
__device__ float g_h   [2*2*BB*HH];          // [s][l][b][h]  carried hidden
__device__ float g_hnew[2*2*BB*HH];          // [s][l][b][h]  fresh GRU hidden
__device__ float g_ctx [2*2*BB*HH];          // [s][o][b][h]  attention context
__device__ float g_es  [2*2*BB*HH];          // [s][l][b][g]  query projection
__device__ float g_buf [2*BB*TT*2*HH];       // [s][b][t][l][h]  hidden history
__device__ float g_eh  [2*BB*TT*2*HH];       // [s][b][t][l][g]  cached history proj
__device__ float g_out [2*TT*BB*HH];         // [s][t][b][h]  top-layer outputs
__device__ float g_gh1 [2*BB*3*HH];          // [s][b][g][h]  h1@Whh1 raw gates (scratch)
__device__ float g_fcp [4*BB*HH];            // [m][n]        fc hnew-half partial

__device__ __forceinline__ float sigm(float x) { return 1.0f / (1.0f + __expf(-x)); }
__device__ __forceinline__ float tanh_fast(float x) {
    float y;
    asm("tanh.approx.f32 %0, %1;" : "=f"(y) : "f"(x));
    return y;
}

__global__ void k_init() {
    int i = blockIdx.x * blockDim.x + threadIdx.x;
    if (i < 2*2*BB*HH) g_h[i] = 0.0f;
}

// ---------------------------------------------------------------------------
// Shared 3-gate GEMM body: acc[r][c][g] += A[b0+2ty+r][k] * W[g*HH+hc0+2tx+c][k]
// Ping-pong smem, LDG prefetch, 1-stage LDS pipeline. sh needs 8640 floats.
// ---------------------------------------------------------------------------
__device__ __forceinline__ void gemm3(float* sh, const float* __restrict__ Asrc,
                                      const float* __restrict__ Wsrc,
                                      int b0, int hc0, int tid, int tx, int ty,
                                      float acc[2][2][3]) {
    float (*As)[32][33]    = (float(*)[32][33])sh;            // [2][32][33]
    float (*Ws)[3][32][34] = (float(*)[3][32][34])(sh + 2112); // [2][3][32][34]
    const int bb = tid >> 3, kq = tid & 7;
    const float* aptr = &Asrc[(b0 + bb)*HH + 4*kq];
    const float* wptr = &Wsrc[(hc0 + bb)*HH + 4*kq];

    float4 pa  = *(const float4*)aptr;
    float4 pw0 = *(const float4*)(wptr);
    float4 pw1 = *(const float4*)(wptr + HH*HH);
    float4 pw2 = *(const float4*)(wptr + 2*HH*HH);

    int buf = 0;
    for (int k0 = 0; k0 < HH; k0 += 32) {
        As[buf][bb][4*kq+0] = pa.x; As[buf][bb][4*kq+1] = pa.y;
        As[buf][bb][4*kq+2] = pa.z; As[buf][bb][4*kq+3] = pa.w;
        Ws[buf][0][4*kq+0][bb] = pw0.x; Ws[buf][0][4*kq+1][bb] = pw0.y;
        Ws[buf][0][4*kq+2][bb] = pw0.z; Ws[buf][0][4*kq+3][bb] = pw0.w;
        Ws[buf][1][4*kq+0][bb] = pw1.x; Ws[buf][1][4*kq+1][bb] = pw1.y;
        Ws[buf][1][4*kq+2][bb] = pw1.z; Ws[buf][1][4*kq+3][bb] = pw1.w;
        Ws[buf][2][4*kq+0][bb] = pw2.x; Ws[buf][2][4*kq+1][bb] = pw2.y;
        Ws[buf][2][4*kq+2][bb] = pw2.z; Ws[buf][2][4*kq+3][bb] = pw2.w;
        __syncthreads();
        if (k0 + 32 < HH) {
            pa  = *(const float4*)(aptr + k0 + 32);
            pw0 = *(const float4*)(wptr + k0 + 32);
            pw1 = *(const float4*)(wptr + HH*HH + k0 + 32);
            pw2 = *(const float4*)(wptr + 2*HH*HH + k0 + 32);
        }
        float a0 = As[buf][2*ty + 0][0], a1 = As[buf][2*ty + 1][0];
        float2 w0 = *(float2*)&Ws[buf][0][0][2*tx];
        float2 w1 = *(float2*)&Ws[buf][1][0][2*tx];
        float2 w2 = *(float2*)&Ws[buf][2][0][2*tx];
#pragma unroll
        for (int kk = 0; kk < 32; kk++) {
            float a0n, a1n; float2 w0n, w1n, w2n;
            if (kk < 31) {
                a0n = As[buf][2*ty + 0][kk+1]; a1n = As[buf][2*ty + 1][kk+1];
                w0n = *(float2*)&Ws[buf][0][kk+1][2*tx];
                w1n = *(float2*)&Ws[buf][1][kk+1][2*tx];
                w2n = *(float2*)&Ws[buf][2][kk+1][2*tx];
            }
            acc[0][0][0] += a0*w0.x; acc[0][1][0] += a0*w0.y;
            acc[0][0][1] += a0*w1.x; acc[0][1][1] += a0*w1.y;
            acc[0][0][2] += a0*w2.x; acc[0][1][2] += a0*w2.y;
            acc[1][0][0] += a1*w0.x; acc[1][1][0] += a1*w0.y;
            acc[1][0][1] += a1*w1.x; acc[1][1][1] += a1*w1.y;
            acc[1][0][2] += a1*w2.x; acc[1][1][2] += a1*w2.y;
            a0 = a0n; a1 = a1n; w0 = w0n; w1 = w1n; w2 = w2n;
        }
        buf ^= 1;
    }
}

// ---------------------------------------------------------------------------
// k3 body: attention projections (es||eh), 64x64 tile, lsel picks layer rows.
// sh needs 8704 floats.
// ---------------------------------------------------------------------------
__device__ __forceinline__ void k3_body(float* sh, const float* __restrict__ attn_W,
                                        int step, int lsel, int bx, int by,
                                        int tid, int tx, int ty) {
    float (*AsT)[32][68] = (float(*)[32][68])sh;           // [2][32][68]
    float (*Bs )[32][68] = (float(*)[32][68])(sh + 4352);  // [2][32][68]
    const int n0 = bx * 64;
    const int byf = ((by & 4) << 1) | (lsel << 2) | (by & 3);
    const int m0 = byf * 64;
    const float* __restrict__ bsrc = (n0 < 256) ? (attn_W + n0*(2*HH))
                                                : (attn_W + (n0 - 256)*(2*HH) + HH);
    float acc[4][4] = {};

    const int mm = tid >> 3, kq = tid & 7;
    const float* aptr0 = &g_hnew[(m0 + mm)*HH + 4*kq];
    const float* aptr1 = &g_hnew[(m0 + mm + 32)*HH + 4*kq];
    const float* bptr0 = &bsrc[mm*(2*HH) + 4*kq];
    const float* bptr1 = &bsrc[(mm + 32)*(2*HH) + 4*kq];

    float4 pa0 = *(const float4*)aptr0;
    float4 pa1 = *(const float4*)aptr1;
    float4 pb0 = *(const float4*)bptr0;
    float4 pb1 = *(const float4*)bptr1;

    int buf = 0;
    for (int k0 = 0; k0 < HH; k0 += 32) {
        AsT[buf][4*kq+0][mm] = pa0.x; AsT[buf][4*kq+1][mm] = pa0.y;
        AsT[buf][4*kq+2][mm] = pa0.z; AsT[buf][4*kq+3][mm] = pa0.w;
        AsT[buf][4*kq+0][mm+32] = pa1.x; AsT[buf][4*kq+1][mm+32] = pa1.y;
        AsT[buf][4*kq+2][mm+32] = pa1.z; AsT[buf][4*kq+3][mm+32] = pa1.w;
        Bs[buf][4*kq+0][mm] = pb0.x; Bs[buf][4*kq+1][mm] = pb0.y;
        Bs[buf][4*kq+2][mm] = pb0.z; Bs[buf][4*kq+3][mm] = pb0.w;
        Bs[buf][4*kq+0][mm+32] = pb1.x; Bs[buf][4*kq+1][mm+32] = pb1.y;
        Bs[buf][4*kq+2][mm+32] = pb1.z; Bs[buf][4*kq+3][mm+32] = pb1.w;
        __syncthreads();
        if (k0 + 32 < HH) {
            pa0 = *(const float4*)(aptr0 + k0 + 32);
            pa1 = *(const float4*)(aptr1 + k0 + 32);
            pb0 = *(const float4*)(bptr0 + k0 + 32);
            pb1 = *(const float4*)(bptr1 + k0 + 32);
        }
        float4 av = *(float4*)&AsT[buf][0][4*ty];
        float4 bv = *(float4*)&Bs [buf][0][4*tx];
#pragma unroll
        for (int kk = 0; kk < 32; kk++) {
            float4 avn, bvn;
            if (kk < 31) {
                avn = *(float4*)&AsT[buf][kk+1][4*ty];
                bvn = *(float4*)&Bs [buf][kk+1][4*tx];
            }
            acc[0][0] += av.x*bv.x; acc[0][1] += av.x*bv.y; acc[0][2] += av.x*bv.z; acc[0][3] += av.x*bv.w;
            acc[1][0] += av.y*bv.x; acc[1][1] += av.y*bv.y; acc[1][2] += av.y*bv.z; acc[1][3] += av.y*bv.w;
            acc[2][0] += av.z*bv.x; acc[2][1] += av.z*bv.y; acc[2][2] += av.z*bv.z; acc[2][3] += av.z*bv.w;
            acc[3][0] += av.w*bv.x; acc[3][1] += av.w*bv.y; acc[3][2] += av.w*bv.z; acc[3][3] += av.w*bv.w;
            av = avn; bv = bvn;
        }
        buf ^= 1;
    }
#pragma unroll
    for (int r = 0; r < 4; r++) {
        int m = m0 + 4*ty + r;
        int s = m >> 9, l = (m >> 8) & 1, b = m & 255;
        if (n0 < 256) {
#pragma unroll
            for (int c = 0; c < 4; c++) g_es[m*HH + n0 + 4*tx + c] = acc[r][c];
        } else {
            float* dst = g_eh + (((s*BB + b)*TT + step)*2 + l)*HH + (n0 - 256) + 4*tx;
#pragma unroll
            for (int c = 0; c < 4; c++) dst[c] = acc[r][c];
        }
    }
}

// ---------------------------------------------------------------------------
// fc GEMM half body: 64m x 32n tile over K=256 of either the ctx half
// (bcol=0, Asrc=g_ctx) or hnew half (bcol=HH, Asrc=g_hnew). sh: 6656 floats.
// ---------------------------------------------------------------------------
__device__ __forceinline__ void gemm_fc(float* sh, const float* __restrict__ Asrc,
                                        const float* __restrict__ fc_W, int bcol,
                                        int n0, int m0, int tid, int tx, int ty,
                                        float acc[4][2]) {
    float (*AsT)[32][68] = (float(*)[32][68])sh;           // [2][32][68]
    float (*Bs )[32][36] = (float(*)[32][36])(sh + 4352);  // [2][32][36]
    const int mm = tid >> 3, kq = tid & 7;
    const float* bptr  = &fc_W[(n0 + mm)*(2*HH) + bcol + 4*kq];
    const float* aptr0 = &Asrc[(m0 + mm)*HH + 4*kq];
    const float* aptr1 = &Asrc[(m0 + mm + 32)*HH + 4*kq];

    float4 pa0 = *(const float4*)aptr0;
    float4 pa1 = *(const float4*)aptr1;
    float4 pb  = *(const float4*)bptr;

    int buf = 0;
    for (int k0 = 0; k0 < HH; k0 += 32) {
        AsT[buf][4*kq+0][mm] = pa0.x; AsT[buf][4*kq+1][mm] = pa0.y;
        AsT[buf][4*kq+2][mm] = pa0.z; AsT[buf][4*kq+3][mm] = pa0.w;
        AsT[buf][4*kq+0][mm+32] = pa1.x; AsT[buf][4*kq+1][mm+32] = pa1.y;
        AsT[buf][4*kq+2][mm+32] = pa1.z; AsT[buf][4*kq+3][mm+32] = pa1.w;
        Bs[buf][4*kq+0][mm] = pb.x; Bs[buf][4*kq+1][mm] = pb.y;
        Bs[buf][4*kq+2][mm] = pb.z; Bs[buf][4*kq+3][mm] = pb.w;
        __syncthreads();
        if (k0 + 32 < HH) {
            pa0 = *(const float4*)(aptr0 + k0 + 32);
            pa1 = *(const float4*)(aptr1 + k0 + 32);
            pb  = *(const float4*)(bptr + k0 + 32);
        }
        float4 av = *(float4*)&AsT[buf][0][4*ty];
        float2 bv = *(float2*)&Bs [buf][0][2*tx];
#pragma unroll
        for (int kk = 0; kk < 32; kk++) {
            float4 avn; float2 bvn;
            if (kk < 31) {
                avn = *(float4*)&AsT[buf][kk+1][4*ty];
                bvn = *(float2*)&Bs [buf][kk+1][2*tx];
            }
            acc[0][0] += av.x*bv.x; acc[0][1] += av.x*bv.y;
            acc[1][0] += av.y*bv.x; acc[1][1] += av.y*bv.y;
            acc[2][0] += av.z*bv.x; acc[2][1] += av.z*bv.y;
            acc[3][0] += av.w*bv.x; acc[3][1] += av.w*bv.y;
            av = avn; bv = bvn;
        }
        buf ^= 1;
    }
}

// ---------------------------------------------------------------------------
// KA: z<2 -> GRU layer 0 (gate math fused); z>=2 -> h1@Whh1 raw-gate GEMM
// into g_gh1 (independent of k1: reads only last step's g_h l=1).
// grid (8 h, 8 b, 4).
// ---------------------------------------------------------------------------
__global__ __launch_bounds__(256) void kA(const float* __restrict__ recv,
                                          GruP p1, GruP p2, int step) {
    __shared__ float sh[8704];
    const int tid = threadIdx.x, tx = tid & 15, ty = tid >> 4;
    const int b0 = blockIdx.y * 32, hc0 = blockIdx.x * 32;
    const int z = blockIdx.z, s = z & 1;
    const GruP P = s ? p2 : p1;
    const bool l0 = (z < 2);

    const float* __restrict__ Asrc = g_h + (s*2 + (l0 ? 0 : 1)) * BB * HH;
    const float* __restrict__ Wsrc = l0 ? P.Whh0 : P.Whh1;
    float acc[2][2][3] = {};
    gemm3(sh, Asrc, Wsrc, b0, hc0, tid, tx, ty, acc);

    if (l0) {
#pragma unroll
        for (int r = 0; r < 2; r++) {
            int b = b0 + 2*ty + r;
            float x0 = recv[(b*TT + step)*2 + 0];
            float x1 = recv[(b*TT + step)*2 + 1];
#pragma unroll
            for (int c = 0; c < 2; c++) {
                int h = hc0 + 2*tx + c;
                float ir  = P.Wih0[h*2]          * x0 + P.Wih0[h*2 + 1]          * x1 + P.bih0[h];
                float iz  = P.Wih0[(HH + h)*2]   * x0 + P.Wih0[(HH + h)*2 + 1]   * x1 + P.bih0[HH + h];
                float in_ = P.Wih0[(2*HH + h)*2] * x0 + P.Wih0[(2*HH + h)*2 + 1] * x1 + P.bih0[2*HH + h];
                float hr = acc[r][c][0] + P.bhh0[h];
                float hz = acc[r][c][1] + P.bhh0[HH + h];
                float hn = acc[r][c][2] + P.bhh0[2*HH + h];
                float rg = sigm(ir + hr);
                float zg = sigm(iz + hz);
                float n  = tanhf(in_ + rg * hn);
                float hv = (1.0f - zg) * n + zg * Asrc[b*HH + h];
                g_hnew[((s*2 + 0)*BB + b)*HH + h] = hv;
                g_buf[(((s*BB + b)*TT + step)*2 + 0)*HH + h] = hv;
            }
        }
    } else {
#pragma unroll
        for (int r = 0; r < 2; r++) {
            int b = b0 + 2*ty + r;
#pragma unroll
            for (int c = 0; c < 2; c++) {
                int h = hc0 + 2*tx + c;
#pragma unroll
                for (int g = 0; g < 3; g++)
                    g_gh1[((s*BB + b)*3 + g)*HH + h] = acc[r][c][g];
            }
        }
    }
}

// ---------------------------------------------------------------------------
// KB: z<2 -> GRU layer 1 gate half (hnew0@Wih1 + stored gh1 + gate math);
// z==2 -> k3 l=0 projections (depend only on k1). grid (8, 8, 2 or 3).
// ---------------------------------------------------------------------------
__global__ __launch_bounds__(256) void kB(GruP p1, GruP p2,
                                          const float* __restrict__ attn_W, int step) {
    __shared__ float sh[8704];
    const int tid = threadIdx.x, tx = tid & 15, ty = tid >> 4;
    if (blockIdx.z == 2) {
        k3_body(sh, attn_W, step, 0, blockIdx.x, blockIdx.y, tid, tx, ty);
        return;
    }
    const int s = blockIdx.z;
    const GruP P = s ? p2 : p1;
    const int b0 = blockIdx.y * 32, hc0 = blockIdx.x * 32;
    const float* __restrict__ xin = g_hnew + (s*2 + 0) * BB * HH;
    const float* __restrict__ hp  = g_h    + (s*2 + 1) * BB * HH;
    float acc[2][2][3] = {};
    gemm3(sh, xin, P.Wih1, b0, hc0, tid, tx, ty, acc);

#pragma unroll
    for (int r = 0; r < 2; r++) {
        int b = b0 + 2*ty + r;
        const float* gh = &g_gh1[(s*BB + b)*3*HH];
#pragma unroll
        for (int c = 0; c < 2; c++) {
            int h = hc0 + 2*tx + c;
            float ir  = acc[r][c][0] + P.bih1[h];
            float iz  = acc[r][c][1] + P.bih1[HH + h];
            float in_ = acc[r][c][2] + P.bih1[2*HH + h];
            float hr  = gh[h]        + P.bhh1[h];
            float hz  = gh[HH + h]   + P.bhh1[HH + h];
            float hn  = gh[2*HH + h] + P.bhh1[2*HH + h];
            float rg = sigm(ir + hr);
            float zg = sigm(iz + hz);
            float n  = tanhf(in_ + rg * hn);
            float hv = (1.0f - zg) * n + zg * hp[b*HH + h];
            g_hnew[((s*2 + 1)*BB + b)*HH + h] = hv;
            g_buf[(((s*BB + b)*TT + step)*2 + 1)*HH + h] = hv;
            g_out[((s*TT + step)*BB + b)*HH + h] = hv;
        }
    }
}

// ---------------------------------------------------------------------------
// KC: k3 l=1 projections (after layer-1 hidden exists). grid (8, 8).
// ---------------------------------------------------------------------------
__global__ __launch_bounds__(256) void kC(const float* __restrict__ attn_W, int step) {
    __shared__ float sh[8704];
    const int tid = threadIdx.x, tx = tid & 15, ty = tid >> 4;
    k3_body(sh, attn_W, step, 1, blockIdx.x, blockIdx.y, tid, tx, ty);
}

// ---------------------------------------------------------------------------
// KD: id<512 -> k4 attention (energies+softmax+context);
// id>=512 -> fc hnew-half partial GEMM into g_fcp (independent of ctx).
// 1D grid of 640.
// ---------------------------------------------------------------------------
__global__ __launch_bounds__(256) void kD(const float* __restrict__ v_W,
                                          const float* __restrict__ fc_W, int step) {
    __shared__ float sh[8704];
    const int tid = threadIdx.x;
    const int id = blockIdx.x;
    if (id >= 512) {
        const int f = id - 512;
        const int tx = tid & 15, ty = tid >> 4;
        const int n0 = (f & 7) * 32, m0 = (f >> 3) * 64;
        float acc[4][2] = {};
        gemm_fc(sh, g_hnew, fc_W, HH, n0, m0, tid, tx, ty, acc);
#pragma unroll
        for (int r = 0; r < 4; r++) {
            int m = m0 + 4*ty + r;
#pragma unroll
            for (int c = 0; c < 2; c++)
                g_fcp[m*HH + n0 + 2*tx + c] = acc[r][c];
        }
        return;
    }
    const int b = id & 255, s = id >> 8;
    const int warp = tid >> 5, lane = tid & 31;
    float* lg  = sh;           // [2][128]
    float* inv = sh + 256;     // [2]
    const int nrows = 2 * (step + 1);

    const int l = warp & 1;
    float esr[8], vw0[8], vw1[8];
    {
        int gb = lane * 8;
        const float* esp = g_es + ((s*2 + l)*BB + b)*HH + gb;
#pragma unroll
        for (int u = 0; u < 8; u++) {
            esr[u] = esp[u];
            vw0[u] = v_W[gb + u];
            vw1[u] = v_W[HH + gb + u];
        }
    }
    const float* ehbase = g_eh + ((s*BB + b)*TT*2) * HH;
    for (int r = warp; r < nrows; r += 8) {
        const float4* ehp = (const float4*)(ehbase + r*HH) + lane*2;
        float4 ea = ehp[0], eb = ehp[1];
        float t0 = 0.0f, t1 = 0.0f, t;
#define ESTEP(u, e) { t = tanh_fast(esr[u] + (e)); t0 += t*vw0[u]; t1 += t*vw1[u]; }
        ESTEP(0, ea.x) ESTEP(1, ea.y) ESTEP(2, ea.z) ESTEP(3, ea.w)
        ESTEP(4, eb.x) ESTEP(5, eb.y) ESTEP(6, eb.z) ESTEP(7, eb.w)
#undef ESTEP
#pragma unroll
        for (int o = 16; o; o >>= 1) {
            t0 += __shfl_xor_sync(0xffffffffu, t0, o);
            t1 += __shfl_xor_sync(0xffffffffu, t1, o);
        }
        if (lane == 0) { lg[0*128 + r] = t0; lg[1*128 + r] = t1; }
    }
    __syncthreads();

    if (warp < 2) {
        int o = warp;
        float m = -1e30f;
        for (int r = lane; r < nrows; r += 32) m = fmaxf(m, lg[o*128 + r]);
#pragma unroll
        for (int off = 16; off; off >>= 1) m = fmaxf(m, __shfl_xor_sync(0xffffffffu, m, off));
        float ss = 0.0f;
        for (int r = lane; r < nrows; r += 32) {
            float e = __expf(lg[o*128 + r] - m);
            lg[o*128 + r] = e;
            ss += e;
        }
#pragma unroll
        for (int off = 16; off; off >>= 1) ss += __shfl_xor_sync(0xffffffffu, ss, off);
        if (lane == 0) inv[o] = 1.0f / ss;
    }
    __syncthreads();

    const float* bufbase = g_buf + ((s*BB + b)*TT*2) * HH;
    float c0 = 0.0f, c1 = 0.0f;
    int r = 0;
    for (; r + 4 <= nrows; r += 4) {
        float v0 = bufbase[(r + 0)*HH + tid];
        float v1 = bufbase[(r + 1)*HH + tid];
        float v2 = bufbase[(r + 2)*HH + tid];
        float v3 = bufbase[(r + 3)*HH + tid];
        c0 += lg[r]*v0 + lg[r+1]*v1 + lg[r+2]*v2 + lg[r+3]*v3;
        c1 += lg[128+r]*v0 + lg[128+r+1]*v1 + lg[128+r+2]*v2 + lg[128+r+3]*v3;
    }
    for (; r < nrows; r++) {
        float v = bufbase[r*HH + tid];
        c0 += lg[r]*v;
        c1 += lg[128 + r]*v;
    }
    g_ctx[((s*2 + 0)*BB + b)*HH + tid] = c0 * inv[0];
    g_ctx[((s*2 + 1)*BB + b)*HH + tid] = c1 * inv[1];
}

// ---------------------------------------------------------------------------
// KE: fc ctx-half GEMM + stored hnew-half partial + bias -> g_h. grid (8, 16).
// ---------------------------------------------------------------------------
__global__ __launch_bounds__(256) void kE(const float* __restrict__ fc_W,
                                          const float* __restrict__ fc_b) {
    __shared__ float sh[8704];
    const int tid = threadIdx.x, tx = tid & 15, ty = tid >> 4;
    const int n0 = blockIdx.x * 32, m0 = blockIdx.y * 64;
    float acc[4][2] = {};
    gemm_fc(sh, g_ctx, fc_W, 0, n0, m0, tid, tx, ty, acc);
#pragma unroll
    for (int r = 0; r < 4; r++) {
        int m = m0 + 4*ty + r;
#pragma unroll
        for (int c = 0; c < 2; c++) {
            int n = n0 + 2*tx + c;
            g_h[m*HH + n] = acc[r][c] + g_fcp[m*HH + n] + fc_b[n];
        }
    }
}

// ---------------------------------------------------------------------------
// K6: final readout: sigmoid([out1 | delayed out2] @ out_W^T + out_b)
// ---------------------------------------------------------------------------
__global__ __launch_bounds__(256) void k6_out(const float* __restrict__ out_W,
                                              const float* __restrict__ out_b,
                                              float* __restrict__ out) {
    const int t = blockIdx.x;
    const int tid = threadIdx.x, warp = tid >> 5, lane = tid & 31;
    __shared__ float w1[HH], w2[HH];
    w1[tid] = out_W[tid];
    w2[tid] = out_W[HH + tid];
    __syncthreads();
    int t2 = (t >= TT - DD - 1) ? (TT - 1) : (t + DD);
    float ob = out_b[0];
    const float* o1b = g_out + ((0*TT + t )*BB) * HH;
    const float* o2b = g_out + ((1*TT + t2)*BB) * HH;
    for (int bb = 0; bb < 32; bb++) {
        int b = warp*32 + bb;
        const float* o1 = o1b + b*HH;
        const float* o2 = o2b + b*HH;
        float acc = 0.0f;
#pragma unroll
        for (int h = lane; h < HH; h += 32) acc += o1[h]*w1[h] + o2[h]*w2[h];
#pragma unroll
        for (int off = 16; off; off >>= 1) acc += __shfl_xor_sync(0xffffffffu, acc, off);
        if (lane == 0) out[b*TT + t] = sigm(acc + ob);
    }
}

// ---------------------------------------------------------------------------
extern "C" void kernel_launch(void* const* d_in, const int* in_sizes, int n_in,
                              void* d_out, int out_size) {
    const float* recv = (const float*)d_in[0];
    GruP p1 { (const float*)d_in[1], (const float*)d_in[2], (const float*)d_in[3], (const float*)d_in[4],
              (const float*)d_in[5], (const float*)d_in[6], (const float*)d_in[7], (const float*)d_in[8] };
    GruP p2 { (const float*)d_in[9],  (const float*)d_in[10], (const float*)d_in[11], (const float*)d_in[12],
              (const float*)d_in[13], (const float*)d_in[14], (const float*)d_in[15], (const float*)d_in[16] };
    const float* fc_W   = (const float*)d_in[17];
    const float* fc_b   = (const float*)d_in[18];
    const float* attn_W = (const float*)d_in[19];
    const float* v_W    = (const float*)d_in[20];
    const float* out_W  = (const float*)d_in[21];
    const float* out_b  = (const float*)d_in[22];
    float* out = (float*)d_out;

    k_init<<<(2*2*BB*HH + 255)/256, 256>>>();

    for (int i = 0; i < TT; i++) {
        const bool attn = (i < TT - 1);   // last step's attention is dead work
        // KA: GRU layer 0 + (independent) h1@Whh1 gate GEMM.
        kA<<<dim3(8, 8, 4), 256>>>(recv, p1, p2, i);
        // KB: GRU layer 1 finish + (independent, k1-only-dependent) k3 l=0.
        kB<<<dim3(8, 8, attn ? 3 : 2), 256>>>(p1, p2, attn_W, i);
        if (attn) {
            kC<<<dim3(8, 8),   256>>>(attn_W, i);       // k3 l=1
            kD<<<640,          256>>>(v_W, fc_W, i);    // k4 + fc hnew-half
            kE<<<dim3(8, 16),  256>>>(fc_W, fc_b);      // fc ctx-half + merge
        }
    }
    k6_out<<<TT, 256>>>(out_W, out_b, out);
}

// round 15
// speedup vs baseline: 1.2807x; 1.2807x over previous
#include <cuda_runtime.h>
#include <math.h>

#define BB 256
#define TT 64
#define HH 256
#define DD 8

struct GruP {
    const float *Wih0, *Whh0, *bih0, *bhh0;
    const float *Wih1, *Whh1, *bih1, *bhh1;
};

// Persistent state (device globals: allocation-free scratch)
__device__ float g_h   [2*2*BB*HH];          // [s][l][b][h]  carried hidden
__device__ float g_hnew[2*2*BB*HH];          // [s][l][b][h]  fresh GRU hidden
__device__ float g_ctx [2*2*BB*HH];          // [s][o][b][h]  attention context
__device__ float g_es  [2*2*BB*HH];          // [s][l][b][g]  query projection
__device__ float g_buf [2*BB*TT*2*HH];       // [s][b][t][l][h]  hidden history
__device__ float g_eh  [2*BB*TT*2*HH];       // [s][b][t][l][g]  cached history proj
__device__ float g_out [2*TT*BB*HH];         // [s][t][b][h]  top-layer outputs

__device__ __forceinline__ float sigm(float x) { return 1.0f / (1.0f + __expf(-x)); }
__device__ __forceinline__ float tanh_fast(float x) {
    float y;
    asm("tanh.approx.f32 %0, %1;" : "=f"(y) : "f"(x));
    return y;
}

__global__ void k_init() {
    int i = blockIdx.x * blockDim.x + threadIdx.x;
    if (i < 2*2*BB*HH) g_h[i] = 0.0f;
}

// ---------------------------------------------------------------------------
// K1: GRU layer 0. gh = h_prev @ Whh0^T fused with gate math.
// 512 threads (16 warps/SM), tile 32b x 32h x 3g, thread = 1b x 2h x 3g.
// Ping-pong smem, LDG prefetch, 1-stage LDS pipeline. grid (8 h, 8 b, 2 s).
// ---------------------------------------------------------------------------
__global__ __launch_bounds__(512) void k1_layer0(const float* __restrict__ recv,
                                                 GruP p1, GruP p2, int step) {
    const int s = blockIdx.z;
    const GruP P = s ? p2 : p1;
    __shared__ float As[2][32][33];        // [buf][b][k]
    __shared__ float Ws[2][3][32][34];     // [buf][g][k][h]
    const int tid = threadIdx.x;
    const int tx = tid & 15, ty = tid >> 4;      // ty 0..31
    const int b0 = blockIdx.y * 32, hc0 = blockIdx.x * 32;
    const float* __restrict__ hprev = g_h + s * 2 * BB * HH;
    float acc[2][3] = {};                        // [h-col][gate]

    const float* aptr = &hprev[(b0 + ty)*HH + 2*tx];
    const float* wptr = &P.Whh0[(hc0 + ty)*HH + 2*tx];
    float2 pa  = *(const float2*)aptr;
    float2 pw0 = *(const float2*)(wptr);
    float2 pw1 = *(const float2*)(wptr + HH*HH);
    float2 pw2 = *(const float2*)(wptr + 2*HH*HH);

    int buf = 0;
    for (int k0 = 0; k0 < HH; k0 += 32) {
        As[buf][ty][2*tx+0] = pa.x; As[buf][ty][2*tx+1] = pa.y;
        Ws[buf][0][2*tx+0][ty] = pw0.x; Ws[buf][0][2*tx+1][ty] = pw0.y;
        Ws[buf][1][2*tx+0][ty] = pw1.x; Ws[buf][1][2*tx+1][ty] = pw1.y;
        Ws[buf][2][2*tx+0][ty] = pw2.x; Ws[buf][2][2*tx+1][ty] = pw2.y;
        __syncthreads();
        if (k0 + 32 < HH) {
            pa  = *(const float2*)(aptr + k0 + 32);
            pw0 = *(const float2*)(wptr + k0 + 32);
            pw1 = *(const float2*)(wptr + HH*HH + k0 + 32);
            pw2 = *(const float2*)(wptr + 2*HH*HH + k0 + 32);
        }
        float a0 = As[buf][ty][0];
        float2 w0 = *(float2*)&Ws[buf][0][0][2*tx];
        float2 w1 = *(float2*)&Ws[buf][1][0][2*tx];
        float2 w2 = *(float2*)&Ws[buf][2][0][2*tx];
#pragma unroll
        for (int kk = 0; kk < 32; kk++) {
            float a0n; float2 w0n, w1n, w2n;
            if (kk < 31) {
                a0n = As[buf][ty][kk+1];
                w0n = *(float2*)&Ws[buf][0][kk+1][2*tx];
                w1n = *(float2*)&Ws[buf][1][kk+1][2*tx];
                w2n = *(float2*)&Ws[buf][2][kk+1][2*tx];
            }
            acc[0][0] += a0*w0.x; acc[1][0] += a0*w0.y;
            acc[0][1] += a0*w1.x; acc[1][1] += a0*w1.y;
            acc[0][2] += a0*w2.x; acc[1][2] += a0*w2.y;
            a0 = a0n; w0 = w0n; w1 = w1n; w2 = w2n;
        }
        buf ^= 1;
    }
    {
        int b = b0 + ty;
        float x0 = recv[(b*TT + step)*2 + 0];
        float x1 = recv[(b*TT + step)*2 + 1];
#pragma unroll
        for (int c = 0; c < 2; c++) {
            int h = hc0 + 2*tx + c;
            float ir  = P.Wih0[h*2]          * x0 + P.Wih0[h*2 + 1]          * x1 + P.bih0[h];
            float iz  = P.Wih0[(HH + h)*2]   * x0 + P.Wih0[(HH + h)*2 + 1]   * x1 + P.bih0[HH + h];
            float in_ = P.Wih0[(2*HH + h)*2] * x0 + P.Wih0[(2*HH + h)*2 + 1] * x1 + P.bih0[2*HH + h];
            float hr = acc[c][0] + P.bhh0[h];
            float hz = acc[c][1] + P.bhh0[HH + h];
            float hn = acc[c][2] + P.bhh0[2*HH + h];
            float rg = sigm(ir + hr);
            float zg = sigm(iz + hz);
            float n  = tanhf(in_ + rg * hn);
            float hv = (1.0f - zg) * n + zg * hprev[b*HH + h];
            g_hnew[((s*2 + 0)*BB + b)*HH + h] = hv;
            g_buf[(((s*BB + b)*TT + step)*2 + 0)*HH + h] = hv;
        }
    }
}

// ---------------------------------------------------------------------------
// K2: GRU layer 1. Two fused GEMMs (hnew0@Wih1, h1@Whh1). 512 threads,
// thread = 1b x 2h x 3g x 2mats. Single-buffered smem (2 syncs), LDG prefetch,
// LDS pipeline. grid (8 h, 8 b, 2 s).
// ---------------------------------------------------------------------------
__global__ __launch_bounds__(512) void k2_layer1(GruP p1, GruP p2, int step) {
    const int s = blockIdx.z;
    const GruP P = s ? p2 : p1;
    __shared__ float A1s[32][33], A2s[32][33];
    __shared__ float Wi[3][32][34], Wh[3][32][34];
    const int tid = threadIdx.x;
    const int tx = tid & 15, ty = tid >> 4;
    const int b0 = blockIdx.y * 32, hc0 = blockIdx.x * 32;
    const float* __restrict__ xin = g_hnew + (s*2 + 0) * BB * HH;
    const float* __restrict__ hp  = g_h    + (s*2 + 1) * BB * HH;
    float ai[2][3] = {}, ah[2][3] = {};

    const float* a1ptr = &xin[(b0 + ty)*HH + 2*tx];
    const float* a2ptr = &hp [(b0 + ty)*HH + 2*tx];
    const float* wiptr = &P.Wih1[(hc0 + ty)*HH + 2*tx];
    const float* whptr = &P.Whh1[(hc0 + ty)*HH + 2*tx];

    float2 pa1 = *(const float2*)a1ptr;
    float2 pa2 = *(const float2*)a2ptr;
    float2 pi0 = *(const float2*)(wiptr);
    float2 pi1 = *(const float2*)(wiptr + HH*HH);
    float2 pi2 = *(const float2*)(wiptr + 2*HH*HH);
    float2 ph0 = *(const float2*)(whptr);
    float2 ph1 = *(const float2*)(whptr + HH*HH);
    float2 ph2 = *(const float2*)(whptr + 2*HH*HH);

    for (int k0 = 0; k0 < HH; k0 += 32) {
        A1s[ty][2*tx+0] = pa1.x; A1s[ty][2*tx+1] = pa1.y;
        A2s[ty][2*tx+0] = pa2.x; A2s[ty][2*tx+1] = pa2.y;
        Wi[0][2*tx+0][ty] = pi0.x; Wi[0][2*tx+1][ty] = pi0.y;
        Wi[1][2*tx+0][ty] = pi1.x; Wi[1][2*tx+1][ty] = pi1.y;
        Wi[2][2*tx+0][ty] = pi2.x; Wi[2][2*tx+1][ty] = pi2.y;
        Wh[0][2*tx+0][ty] = ph0.x; Wh[0][2*tx+1][ty] = ph0.y;
        Wh[1][2*tx+0][ty] = ph1.x; Wh[1][2*tx+1][ty] = ph1.y;
        Wh[2][2*tx+0][ty] = ph2.x; Wh[2][2*tx+1][ty] = ph2.y;
        __syncthreads();
        if (k0 + 32 < HH) {
            pa1 = *(const float2*)(a1ptr + k0 + 32);
            pa2 = *(const float2*)(a2ptr + k0 + 32);
            pi0 = *(const float2*)(wiptr + k0 + 32);
            pi1 = *(const float2*)(wiptr + HH*HH + k0 + 32);
            pi2 = *(const float2*)(wiptr + 2*HH*HH + k0 + 32);
            ph0 = *(const float2*)(whptr + k0 + 32);
            ph1 = *(const float2*)(whptr + HH*HH + k0 + 32);
            ph2 = *(const float2*)(whptr + 2*HH*HH + k0 + 32);
        }
        float x0v = A1s[ty][0], h0v = A2s[ty][0];
        float2 wi0 = *(float2*)&Wi[0][0][2*tx];
        float2 wi1 = *(float2*)&Wi[1][0][2*tx];
        float2 wi2 = *(float2*)&Wi[2][0][2*tx];
        float2 wh0 = *(float2*)&Wh[0][0][2*tx];
        float2 wh1 = *(float2*)&Wh[1][0][2*tx];
        float2 wh2 = *(float2*)&Wh[2][0][2*tx];
#pragma unroll
        for (int kk = 0; kk < 32; kk++) {
            float x0n, h0n;
            float2 wi0n, wi1n, wi2n, wh0n, wh1n, wh2n;
            if (kk < 31) {
                x0n = A1s[ty][kk+1]; h0n = A2s[ty][kk+1];
                wi0n = *(float2*)&Wi[0][kk+1][2*tx];
                wi1n = *(float2*)&Wi[1][kk+1][2*tx];
                wi2n = *(float2*)&Wi[2][kk+1][2*tx];
                wh0n = *(float2*)&Wh[0][kk+1][2*tx];
                wh1n = *(float2*)&Wh[1][kk+1][2*tx];
                wh2n = *(float2*)&Wh[2][kk+1][2*tx];
            }
            ai[0][0] += x0v*wi0.x; ai[1][0] += x0v*wi0.y;
            ai[0][1] += x0v*wi1.x; ai[1][1] += x0v*wi1.y;
            ai[0][2] += x0v*wi2.x; ai[1][2] += x0v*wi2.y;
            ah[0][0] += h0v*wh0.x; ah[1][0] += h0v*wh0.y;
            ah[0][1] += h0v*wh1.x; ah[1][1] += h0v*wh1.y;
            ah[0][2] += h0v*wh2.x; ah[1][2] += h0v*wh2.y;
            x0v = x0n; h0v = h0n;
            wi0 = wi0n; wi1 = wi1n; wi2 = wi2n;
            wh0 = wh0n; wh1 = wh1n; wh2 = wh2n;
        }
        __syncthreads();
    }
    {
        int b = b0 + ty;
#pragma unroll
        for (int c = 0; c < 2; c++) {
            int h = hc0 + 2*tx + c;
            float ir  = ai[c][0] + P.bih1[h];
            float iz  = ai[c][1] + P.bih1[HH + h];
            float in_ = ai[c][2] + P.bih1[2*HH + h];
            float hr  = ah[c][0] + P.bhh1[h];
            float hz  = ah[c][1] + P.bhh1[HH + h];
            float hn  = ah[c][2] + P.bhh1[2*HH + h];
            float rg = sigm(ir + hr);
            float zg = sigm(iz + hz);
            float n  = tanhf(in_ + rg * hn);
            float hv = (1.0f - zg) * n + zg * hp[b*HH + h];
            g_hnew[((s*2 + 1)*BB + b)*HH + h] = hv;
            g_buf[(((s*BB + b)*TT + step)*2 + 1)*HH + h] = hv;
            g_out[((s*TT + step)*BB + b)*HH + h] = hv;
        }
    }
}

// ---------------------------------------------------------------------------
// K3: attention projections. GEMM M=1024, N=512 (es||eh), K=256.
// 512 threads, 64x64 tile, thread = 2m x 4n. Ping-pong smem, LDG prefetch,
// LDS pipeline. grid (8 n, 16 m).
// ---------------------------------------------------------------------------
__global__ __launch_bounds__(512) void k3_proj(const float* __restrict__ attn_W, int step) {
    __shared__ float AsT[2][32][68];  // [buf][k][m]
    __shared__ float Bs [2][32][68];  // [buf][k][n]
    const int tid = threadIdx.x;
    const int tx = tid & 15, ty = tid >> 4;    // ty 0..31
    const int n0 = blockIdx.x * 64, m0 = blockIdx.y * 64;
    const float* __restrict__ bsrc = (n0 < 256) ? (attn_W + n0*(2*HH))
                                                : (attn_W + (n0 - 256)*(2*HH) + HH);
    float acc[2][4] = {};

    const int mm = tid >> 3, kq = tid & 7;     // mm 0..63
    const float* aptr = &g_hnew[(m0 + mm)*HH + 4*kq];
    const float* bptr = &bsrc[mm*(2*HH) + 4*kq];

    float4 pa = *(const float4*)aptr;
    float4 pb = *(const float4*)bptr;

    int buf = 0;
    for (int k0 = 0; k0 < HH; k0 += 32) {
        AsT[buf][4*kq+0][mm] = pa.x; AsT[buf][4*kq+1][mm] = pa.y;
        AsT[buf][4*kq+2][mm] = pa.z; AsT[buf][4*kq+3][mm] = pa.w;
        Bs[buf][4*kq+0][mm] = pb.x; Bs[buf][4*kq+1][mm] = pb.y;
        Bs[buf][4*kq+2][mm] = pb.z; Bs[buf][4*kq+3][mm] = pb.w;
        __syncthreads();
        if (k0 + 32 < HH) {
            pa = *(const float4*)(aptr + k0 + 32);
            pb = *(const float4*)(bptr + k0 + 32);
        }
        float2 av = *(float2*)&AsT[buf][0][2*ty];
        float4 bv = *(float4*)&Bs [buf][0][4*tx];
#pragma unroll
        for (int kk = 0; kk < 32; kk++) {
            float2 avn; float4 bvn;
            if (kk < 31) {
                avn = *(float2*)&AsT[buf][kk+1][2*ty];
                bvn = *(float4*)&Bs [buf][kk+1][4*tx];
            }
            acc[0][0] += av.x*bv.x; acc[0][1] += av.x*bv.y; acc[0][2] += av.x*bv.z; acc[0][3] += av.x*bv.w;
            acc[1][0] += av.y*bv.x; acc[1][1] += av.y*bv.y; acc[1][2] += av.y*bv.z; acc[1][3] += av.y*bv.w;
            av = avn; bv = bvn;
        }
        buf ^= 1;
    }
#pragma unroll
    for (int r = 0; r < 2; r++) {
        int m = m0 + 2*ty + r;
        int s = m >> 9, l = (m >> 8) & 1, b = m & 255;
        if (n0 < 256) {
#pragma unroll
            for (int c = 0; c < 4; c++) g_es[m*HH + n0 + 4*tx + c] = acc[r][c];
        } else {
            float* dst = g_eh + (((s*BB + b)*TT + step)*2 + l)*HH + (n0 - 256) + 4*tx;
#pragma unroll
            for (int c = 0; c < 4; c++) dst[c] = acc[r][c];
        }
    }
}

// ---------------------------------------------------------------------------
// K4: attention energies (tanh.approx) + softmax + context. Block per (b, s).
// ---------------------------------------------------------------------------
__global__ __launch_bounds__(256) void k4_attend(const float* __restrict__ v_W, int step) {
    const int b = blockIdx.x, s = blockIdx.y;
    const int tid = threadIdx.x, warp = tid >> 5, lane = tid & 31;
    __shared__ float lg[2][2*TT];
    __shared__ float inv[2];
    const int nrows = 2 * (step + 1);

    const int l = warp & 1;
    float esr[8], vw0[8], vw1[8];
    {
        int gb = lane * 8;
        const float* esp = g_es + ((s*2 + l)*BB + b)*HH + gb;
#pragma unroll
        for (int u = 0; u < 8; u++) {
            esr[u] = esp[u];
            vw0[u] = v_W[gb + u];
            vw1[u] = v_W[HH + gb + u];
        }
    }
    const float* ehbase = g_eh + ((s*BB + b)*TT*2) * HH;
    for (int r = warp; r < nrows; r += 8) {
        const float4* ehp = (const float4*)(ehbase + r*HH) + lane*2;
        float4 ea = ehp[0], eb = ehp[1];
        float t0 = 0.0f, t1 = 0.0f, t;
#define ESTEP(u, e) { t = tanh_fast(esr[u] + (e)); t0 += t*vw0[u]; t1 += t*vw1[u]; }
        ESTEP(0, ea.x) ESTEP(1, ea.y) ESTEP(2, ea.z) ESTEP(3, ea.w)
        ESTEP(4, eb.x) ESTEP(5, eb.y) ESTEP(6, eb.z) ESTEP(7, eb.w)
#undef ESTEP
#pragma unroll
        for (int o = 16; o; o >>= 1) {
            t0 += __shfl_xor_sync(0xffffffffu, t0, o);
            t1 += __shfl_xor_sync(0xffffffffu, t1, o);
        }
        if (lane == 0) { lg[0][r] = t0; lg[1][r] = t1; }
    }
    __syncthreads();

    if (warp < 2) {
        int o = warp;
        float m = -1e30f;
        for (int r = lane; r < nrows; r += 32) m = fmaxf(m, lg[o][r]);
#pragma unroll
        for (int off = 16; off; off >>= 1) m = fmaxf(m, __shfl_xor_sync(0xffffffffu, m, off));
        float ss = 0.0f;
        for (int r = lane; r < nrows; r += 32) {
            float e = __expf(lg[o][r] - m);
            lg[o][r] = e;
            ss += e;
        }
#pragma unroll
        for (int off = 16; off; off >>= 1) ss += __shfl_xor_sync(0xffffffffu, ss, off);
        if (lane == 0) inv[o] = 1.0f / ss;
    }
    __syncthreads();

    const float* bufbase = g_buf + ((s*BB + b)*TT*2) * HH;
    float c0 = 0.0f, c1 = 0.0f;
    int r = 0;
    for (; r + 4 <= nrows; r += 4) {
        float v0 = bufbase[(r + 0)*HH + tid];
        float v1 = bufbase[(r + 1)*HH + tid];
        float v2 = bufbase[(r + 2)*HH + tid];
        float v3 = bufbase[(r + 3)*HH + tid];
        c0 += lg[0][r]*v0 + lg[0][r+1]*v1 + lg[0][r+2]*v2 + lg[0][r+3]*v3;
        c1 += lg[1][r]*v0 + lg[1][r+1]*v1 + lg[1][r+2]*v2 + lg[1][r+3]*v3;
    }
    for (; r < nrows; r++) {
        float v = bufbase[r*HH + tid];
        c0 += lg[0][r]*v;
        c1 += lg[1][r]*v;
    }
    g_ctx[((s*2 + 0)*BB + b)*HH + tid] = c0 * inv[0];
    g_ctx[((s*2 + 1)*BB + b)*HH + tid] = c1 * inv[1];
}

// ---------------------------------------------------------------------------
// K5: fc merge. GEMM M=1024, N=256, K=512 (A=[ctx|hnew]).
// 512 threads, 64m x 32n tile, thread = 2m x 2n. Ping-pong smem, LDG prefetch,
// LDS pipeline. grid (8 n, 16 m).
// ---------------------------------------------------------------------------
__global__ __launch_bounds__(512) void k5_fc(const float* __restrict__ fc_W,
                                             const float* __restrict__ fc_b) {
    __shared__ float AsT[2][32][68];  // [buf][k][m]
    __shared__ float Bs [2][32][36];  // [buf][k][n]
    const int tid = threadIdx.x;
    const int tx = tid & 15, ty = tid >> 4;    // ty 0..31
    const int n0 = blockIdx.x * 32, m0 = blockIdx.y * 64;
    float acc[2][2] = {};

    const int mm = tid >> 3, kq = tid & 7;     // mm 0..63
    const float* bptr = &fc_W[(n0 + (mm & 31))*(2*HH) + 4*kq];

    auto loadA = [&](int k0, float4& a) {
        const float* Asrc = (k0 < HH) ? g_ctx : g_hnew;
        const int ko = (k0 < HH) ? k0 : (k0 - HH);
        a = *(const float4*)&Asrc[(m0 + mm)*HH + ko + 4*kq];
    };

    float4 pa, pb;
    loadA(0, pa);
    if (tid < 256) pb = *(const float4*)bptr;

    int buf = 0;
    for (int k0 = 0; k0 < 2*HH; k0 += 32) {
        AsT[buf][4*kq+0][mm] = pa.x; AsT[buf][4*kq+1][mm] = pa.y;
        AsT[buf][4*kq+2][mm] = pa.z; AsT[buf][4*kq+3][mm] = pa.w;
        if (tid < 256) {
            Bs[buf][4*kq+0][mm] = pb.x; Bs[buf][4*kq+1][mm] = pb.y;
            Bs[buf][4*kq+2][mm] = pb.z; Bs[buf][4*kq+3][mm] = pb.w;
        }
        __syncthreads();
        if (k0 + 32 < 2*HH) {
            loadA(k0 + 32, pa);
            if (tid < 256) pb = *(const float4*)(bptr + k0 + 32);
        }
        float2 av = *(float2*)&AsT[buf][0][2*ty];
        float2 bv = *(float2*)&Bs [buf][0][2*tx];
#pragma unroll
        for (int kk = 0; kk < 32; kk++) {
            float2 avn, bvn;
            if (kk < 31) {
                avn = *(float2*)&AsT[buf][kk+1][2*ty];
                bvn = *(float2*)&Bs [buf][kk+1][2*tx];
            }
            acc[0][0] += av.x*bv.x; acc[0][1] += av.x*bv.y;
            acc[1][0] += av.y*bv.x; acc[1][1] += av.y*bv.y;
            av = avn; bv = bvn;
        }
        buf ^= 1;
    }
#pragma unroll
    for (int r = 0; r < 2; r++) {
        int m = m0 + 2*ty + r;
#pragma unroll
        for (int c = 0; c < 2; c++) {
            int n = n0 + 2*tx + c;
            g_h[m*HH + n] = acc[r][c] + fc_b[n];
        }
    }
}

// ---------------------------------------------------------------------------
// K6: final readout: sigmoid([out1 | delayed out2] @ out_W^T + out_b)
// ---------------------------------------------------------------------------
__global__ __launch_bounds__(256) void k6_out(const float* __restrict__ out_W,
                                              const float* __restrict__ out_b,
                                              float* __restrict__ out) {
    const int t = blockIdx.x;
    const int tid = threadIdx.x, warp = tid >> 5, lane = tid & 31;
    __shared__ float w1[HH], w2[HH];
    w1[tid] = out_W[tid];
    w2[tid] = out_W[HH + tid];
    __syncthreads();
    int t2 = (t >= TT - DD - 1) ? (TT - 1) : (t + DD);
    float ob = out_b[0];
    const float* o1b = g_out + ((0*TT + t )*BB) * HH;
    const float* o2b = g_out + ((1*TT + t2)*BB) * HH;
    for (int bb = 0; bb < 32; bb++) {
        int b = warp*32 + bb;
        const float* o1 = o1b + b*HH;
        const float* o2 = o2b + b*HH;
        float acc = 0.0f;
#pragma unroll
        for (int h = lane; h < HH; h += 32) acc += o1[h]*w1[h] + o2[h]*w2[h];
#pragma unroll
        for (int off = 16; off; off >>= 1) acc += __shfl_xor_sync(0xffffffffu, acc, off);
        if (lane == 0) out[b*TT + t] = sigm(acc + ob);
    }
}

// ---------------------------------------------------------------------------
extern "C" void kernel_launch(void* const* d_in, const int* in_sizes, int n_in,
                              void* d_out, int out_size) {
    const float* recv = (const float*)d_in[0];
    GruP p1 { (const float*)d_in[1], (const float*)d_in[2], (const float*)d_in[3], (const float*)d_in[4],
              (const float*)d_in[5], (const float*)d_in[6], (const float*)d_in[7], (const float*)d_in[8] };
    GruP p2 { (const float*)d_in[9],  (const float*)d_in[10], (const float*)d_in[11], (const float*)d_in[12],
              (const float*)d_in[13], (const float*)d_in[14], (const float*)d_in[15], (const float*)d_in[16] };
    const float* fc_W   = (const float*)d_in[17];
    const float* fc_b   = (const float*)d_in[18];
    const float* attn_W = (const float*)d_in[19];
    const float* v_W    = (const float*)d_in[20];
    const float* out_W  = (const float*)d_in[21];
    const float* out_b  = (const float*)d_in[22];
    float* out = (float*)d_out;

    k_init<<<(2*2*BB*HH + 255)/256, 256>>>();

    for (int i = 0; i < TT; i++) {
        k1_layer0<<<dim3(8, 8, 2), 512>>>(recv, p1, p2, i);
        k2_layer1<<<dim3(8, 8, 2), 512>>>(p1, p2, i);
        if (i < TT - 1) {   // attention+fc only feed the NEXT step's hidden state
            k3_proj  <<<dim3(8, 16), 512>>>(attn_W, i);
            k4_attend<<<dim3(BB, 2), 256>>>(v_W, i);
            k5_fc    <<<dim3(8, 16), 512>>>(fc_W, fc_b);
        }
    }
    k6_out<<<TT, 256>>>(out_W, out_b, out);
}

// round 16
// speedup vs baseline: 1.7402x; 1.3588x over previous
#include <cuda_runtime.h>
#include <math.h>

#define BB 256
#define TT 64
#define HH 256
#define DD 8

struct GruP {
    const float *Wih0, *Whh0, *bih0, *bhh0;
    const float *Wih1, *Whh1, *bih1, *bhh1;
};

// Persistent state (device globals: allocation-free scratch)
__device__ float g_h   [2*2*BB*HH];          // [s][l][b][h]  carried hidden
__device__ float g_hnew[2*2*BB*HH];          // [s][l][b][h]  fresh GRU hidden
__device__ float g_ctx [2*2*BB*HH];          // [s][o][b][h]  attention context
__device__ float g_es  [2*2*BB*HH];          // [s][l][b][g]  query projection
__device__ float g_buf [2*BB*TT*2*HH];       // [s][b][t][l][h]  hidden history
__device__ float g_eh  [2*BB*TT*2*HH];       // [s][b][t][l][g]  cached history proj
__device__ float g_out [2*TT*BB*HH];         // [s][t][b][h]  top-layer outputs

__device__ __forceinline__ float sigm(float x) { return 1.0f / (1.0f + __expf(-x)); }
__device__ __forceinline__ float tanh_fast(float x) {
    float y;
    asm("tanh.approx.f32 %0, %1;" : "=f"(y) : "f"(x));
    return y;
}

// ---- tf32 MMA helpers (2xTF32 compensated: hi*hi + hi*lo + lo*hi) ----
__device__ __forceinline__ unsigned cvt_tf32(float x) {
    unsigned u; asm("cvt.rna.tf32.f32 %0, %1;" : "=r"(u) : "f"(x)); return u;
}
__device__ __forceinline__ void split_tf32(float v, unsigned& hi, unsigned& lo) {
    hi = cvt_tf32(v);
    lo = cvt_tf32(v - __uint_as_float(hi));
}
__device__ __forceinline__ void mma8(float* c, const unsigned* a, const unsigned* b) {
    asm volatile("mma.sync.aligned.m16n8k8.row.col.f32.tf32.tf32.f32 "
        "{%0,%1,%2,%3}, {%4,%5,%6,%7}, {%8,%9}, {%0,%1,%2,%3};"
        : "+f"(c[0]), "+f"(c[1]), "+f"(c[2]), "+f"(c[3])
        : "r"(a[0]), "r"(a[1]), "r"(a[2]), "r"(a[3]), "r"(b[0]), "r"(b[1]));
}

__global__ void k_init() {
    int i = blockIdx.x * blockDim.x + threadIdx.x;
    if (i < 2*2*BB*HH) g_h[i] = 0.0f;
}

// ---------------------------------------------------------------------------
// K1: GRU layer 0 (R9 version). gh = h_prev @ Whh0^T fused with gate math.
// ---------------------------------------------------------------------------
__global__ __launch_bounds__(256) void k1_layer0(const float* __restrict__ recv,
                                                 GruP p1, GruP p2, int step) {
    const int s = blockIdx.z;
    const GruP P = s ? p2 : p1;
    __shared__ float As[2][32][33];
    __shared__ float Ws[2][3][32][34];
    const int tid = threadIdx.x;
    const int tx = tid & 15, ty = tid >> 4;
    const int b0 = blockIdx.y * 32, hc0 = blockIdx.x * 32;
    const float* __restrict__ hprev = g_h + s * 2 * BB * HH;
    float acc[2][2][3] = {};

    const int bb = tid >> 3, kq = tid & 7;
    const float* aptr = &hprev[(b0 + bb)*HH + 4*kq];
    const float* wptr = &P.Whh0[(hc0 + bb)*HH + 4*kq];

    float4 pa  = *(const float4*)aptr;
    float4 pw0 = *(const float4*)(wptr);
    float4 pw1 = *(const float4*)(wptr + HH*HH);
    float4 pw2 = *(const float4*)(wptr + 2*HH*HH);

    int buf = 0;
    for (int k0 = 0; k0 < HH; k0 += 32) {
        As[buf][bb][4*kq+0] = pa.x; As[buf][bb][4*kq+1] = pa.y;
        As[buf][bb][4*kq+2] = pa.z; As[buf][bb][4*kq+3] = pa.w;
        Ws[buf][0][4*kq+0][bb] = pw0.x; Ws[buf][0][4*kq+1][bb] = pw0.y;
        Ws[buf][0][4*kq+2][bb] = pw0.z; Ws[buf][0][4*kq+3][bb] = pw0.w;
        Ws[buf][1][4*kq+0][bb] = pw1.x; Ws[buf][1][4*kq+1][bb] = pw1.y;
        Ws[buf][1][4*kq+2][bb] = pw1.z; Ws[buf][1][4*kq+3][bb] = pw1.w;
        Ws[buf][2][4*kq+0][bb] = pw2.x; Ws[buf][2][4*kq+1][bb] = pw2.y;
        Ws[buf][2][4*kq+2][bb] = pw2.z; Ws[buf][2][4*kq+3][bb] = pw2.w;
        __syncthreads();
        if (k0 + 32 < HH) {
            pa  = *(const float4*)(aptr + k0 + 32);
            pw0 = *(const float4*)(wptr + k0 + 32);
            pw1 = *(const float4*)(wptr + HH*HH + k0 + 32);
            pw2 = *(const float4*)(wptr + 2*HH*HH + k0 + 32);
        }
        float a0 = As[buf][2*ty + 0][0], a1 = As[buf][2*ty + 1][0];
        float2 w0 = *(float2*)&Ws[buf][0][0][2*tx];
        float2 w1 = *(float2*)&Ws[buf][1][0][2*tx];
        float2 w2 = *(float2*)&Ws[buf][2][0][2*tx];
#pragma unroll
        for (int kk = 0; kk < 32; kk++) {
            float a0n, a1n; float2 w0n, w1n, w2n;
            if (kk < 31) {
                a0n = As[buf][2*ty + 0][kk+1]; a1n = As[buf][2*ty + 1][kk+1];
                w0n = *(float2*)&Ws[buf][0][kk+1][2*tx];
                w1n = *(float2*)&Ws[buf][1][kk+1][2*tx];
                w2n = *(float2*)&Ws[buf][2][kk+1][2*tx];
            }
            acc[0][0][0] += a0*w0.x; acc[0][1][0] += a0*w0.y;
            acc[0][0][1] += a0*w1.x; acc[0][1][1] += a0*w1.y;
            acc[0][0][2] += a0*w2.x; acc[0][1][2] += a0*w2.y;
            acc[1][0][0] += a1*w0.x; acc[1][1][0] += a1*w0.y;
            acc[1][0][1] += a1*w1.x; acc[1][1][1] += a1*w1.y;
            acc[1][0][2] += a1*w2.x; acc[1][1][2] += a1*w2.y;
            a0 = a0n; a1 = a1n; w0 = w0n; w1 = w1n; w2 = w2n;
        }
        buf ^= 1;
    }
#pragma unroll
    for (int r = 0; r < 2; r++) {
        int b = b0 + 2*ty + r;
        float x0 = recv[(b*TT + step)*2 + 0];
        float x1 = recv[(b*TT + step)*2 + 1];
#pragma unroll
        for (int c = 0; c < 2; c++) {
            int h = hc0 + 2*tx + c;
            float ir  = P.Wih0[h*2]          * x0 + P.Wih0[h*2 + 1]          * x1 + P.bih0[h];
            float iz  = P.Wih0[(HH + h)*2]   * x0 + P.Wih0[(HH + h)*2 + 1]   * x1 + P.bih0[HH + h];
            float in_ = P.Wih0[(2*HH + h)*2] * x0 + P.Wih0[(2*HH + h)*2 + 1] * x1 + P.bih0[2*HH + h];
            float hr = acc[r][c][0] + P.bhh0[h];
            float hz = acc[r][c][1] + P.bhh0[HH + h];
            float hn = acc[r][c][2] + P.bhh0[2*HH + h];
            float rg = sigm(ir + hr);
            float zg = sigm(iz + hz);
            float n  = tanhf(in_ + rg * hn);
            float hv = (1.0f - zg) * n + zg * hprev[b*HH + h];
            g_hnew[((s*2 + 0)*BB + b)*HH + h] = hv;
            g_buf[(((s*BB + b)*TT + step)*2 + 0)*HH + h] = hv;
        }
    }
}

// ---------------------------------------------------------------------------
// K2: GRU layer 1 (R9 version). Two fused GEMMs.
// ---------------------------------------------------------------------------
__global__ __launch_bounds__(256) void k2_layer1(GruP p1, GruP p2, int step) {
    const int s = blockIdx.z;
    const GruP P = s ? p2 : p1;
    __shared__ float A1s[32][33], A2s[32][33];
    __shared__ float Wi[3][32][34], Wh[3][32][34];
    const int tid = threadIdx.x;
    const int tx = tid & 15, ty = tid >> 4;
    const int b0 = blockIdx.y * 32, hc0 = blockIdx.x * 32;
    const float* __restrict__ xin = g_hnew + (s*2 + 0) * BB * HH;
    const float* __restrict__ hp  = g_h    + (s*2 + 1) * BB * HH;
    float ai[2][2][3] = {}, ah[2][2][3] = {};

    const int bb = tid >> 3, kq = tid & 7;
    const float* a1ptr = &xin[(b0 + bb)*HH + 4*kq];
    const float* a2ptr = &hp [(b0 + bb)*HH + 4*kq];
    const float* wiptr = &P.Wih1[(hc0 + bb)*HH + 4*kq];
    const float* whptr = &P.Whh1[(hc0 + bb)*HH + 4*kq];

    float4 pa1 = *(const float4*)a1ptr;
    float4 pa2 = *(const float4*)a2ptr;
    float4 pi0 = *(const float4*)(wiptr);
    float4 pi1 = *(const float4*)(wiptr + HH*HH);
    float4 pi2 = *(const float4*)(wiptr + 2*HH*HH);
    float4 ph0 = *(const float4*)(whptr);
    float4 ph1 = *(const float4*)(whptr + HH*HH);
    float4 ph2 = *(const float4*)(whptr + 2*HH*HH);

    for (int k0 = 0; k0 < HH; k0 += 32) {
        A1s[bb][4*kq+0] = pa1.x; A1s[bb][4*kq+1] = pa1.y;
        A1s[bb][4*kq+2] = pa1.z; A1s[bb][4*kq+3] = pa1.w;
        A2s[bb][4*kq+0] = pa2.x; A2s[bb][4*kq+1] = pa2.y;
        A2s[bb][4*kq+2] = pa2.z; A2s[bb][4*kq+3] = pa2.w;
        Wi[0][4*kq+0][bb] = pi0.x; Wi[0][4*kq+1][bb] = pi0.y;
        Wi[0][4*kq+2][bb] = pi0.z; Wi[0][4*kq+3][bb] = pi0.w;
        Wi[1][4*kq+0][bb] = pi1.x; Wi[1][4*kq+1][bb] = pi1.y;
        Wi[1][4*kq+2][bb] = pi1.z; Wi[1][4*kq+3][bb] = pi1.w;
        Wi[2][4*kq+0][bb] = pi2.x; Wi[2][4*kq+1][bb] = pi2.y;
        Wi[2][4*kq+2][bb] = pi2.z; Wi[2][4*kq+3][bb] = pi2.w;
        Wh[0][4*kq+0][bb] = ph0.x; Wh[0][4*kq+1][bb] = ph0.y;
        Wh[0][4*kq+2][bb] = ph0.z; Wh[0][4*kq+3][bb] = ph0.w;
        Wh[1][4*kq+0][bb] = ph1.x; Wh[1][4*kq+1][bb] = ph1.y;
        Wh[1][4*kq+2][bb] = ph1.z; Wh[1][4*kq+3][bb] = ph1.w;
        Wh[2][4*kq+0][bb] = ph2.x; Wh[2][4*kq+1][bb] = ph2.y;
        Wh[2][4*kq+2][bb] = ph2.z; Wh[2][4*kq+3][bb] = ph2.w;
        __syncthreads();
        if (k0 + 32 < HH) {
            pa1 = *(const float4*)(a1ptr + k0 + 32);
            pa2 = *(const float4*)(a2ptr + k0 + 32);
            pi0 = *(const float4*)(wiptr + k0 + 32);
            pi1 = *(const float4*)(wiptr + HH*HH + k0 + 32);
            pi2 = *(const float4*)(wiptr + 2*HH*HH + k0 + 32);
            ph0 = *(const float4*)(whptr + k0 + 32);
            ph1 = *(const float4*)(whptr + HH*HH + k0 + 32);
            ph2 = *(const float4*)(whptr + 2*HH*HH + k0 + 32);
        }
        float x0v = A1s[2*ty + 0][0], x1v = A1s[2*ty + 1][0];
        float h0v = A2s[2*ty + 0][0], h1v = A2s[2*ty + 1][0];
        float2 wi0 = *(float2*)&Wi[0][0][2*tx];
        float2 wi1 = *(float2*)&Wi[1][0][2*tx];
        float2 wi2 = *(float2*)&Wi[2][0][2*tx];
        float2 wh0 = *(float2*)&Wh[0][0][2*tx];
        float2 wh1 = *(float2*)&Wh[1][0][2*tx];
        float2 wh2 = *(float2*)&Wh[2][0][2*tx];
#pragma unroll
        for (int kk = 0; kk < 32; kk++) {
            float x0n, x1n, h0n, h1n;
            float2 wi0n, wi1n, wi2n, wh0n, wh1n, wh2n;
            if (kk < 31) {
                x0n = A1s[2*ty + 0][kk+1]; x1n = A1s[2*ty + 1][kk+1];
                h0n = A2s[2*ty + 0][kk+1]; h1n = A2s[2*ty + 1][kk+1];
                wi0n = *(float2*)&Wi[0][kk+1][2*tx];
                wi1n = *(float2*)&Wi[1][kk+1][2*tx];
                wi2n = *(float2*)&Wi[2][kk+1][2*tx];
                wh0n = *(float2*)&Wh[0][kk+1][2*tx];
                wh1n = *(float2*)&Wh[1][kk+1][2*tx];
                wh2n = *(float2*)&Wh[2][kk+1][2*tx];
            }
            ai[0][0][0] += x0v*wi0.x; ai[0][1][0] += x0v*wi0.y;
            ai[1][0][0] += x1v*wi0.x; ai[1][1][0] += x1v*wi0.y;
            ai[0][0][1] += x0v*wi1.x; ai[0][1][1] += x0v*wi1.y;
            ai[1][0][1] += x1v*wi1.x; ai[1][1][1] += x1v*wi1.y;
            ai[0][0][2] += x0v*wi2.x; ai[0][1][2] += x0v*wi2.y;
            ai[1][0][2] += x1v*wi2.x; ai[1][1][2] += x1v*wi2.y;
            ah[0][0][0] += h0v*wh0.x; ah[0][1][0] += h0v*wh0.y;
            ah[1][0][0] += h1v*wh0.x; ah[1][1][0] += h1v*wh0.y;
            ah[0][0][1] += h0v*wh1.x; ah[0][1][1] += h0v*wh1.y;
            ah[1][0][1] += h1v*wh1.x; ah[1][1][1] += h1v*wh1.y;
            ah[0][0][2] += h0v*wh2.x; ah[0][1][2] += h0v*wh2.y;
            ah[1][0][2] += h1v*wh2.x; ah[1][1][2] += h1v*wh2.y;
            x0v = x0n; x1v = x1n; h0v = h0n; h1v = h1n;
            wi0 = wi0n; wi1 = wi1n; wi2 = wi2n;
            wh0 = wh0n; wh1 = wh1n; wh2 = wh2n;
        }
        __syncthreads();
    }
#pragma unroll
    for (int r = 0; r < 2; r++) {
        int b = b0 + 2*ty + r;
#pragma unroll
        for (int c = 0; c < 2; c++) {
            int h = hc0 + 2*tx + c;
            float ir  = ai[r][c][0] + P.bih1[h];
            float iz  = ai[r][c][1] + P.bih1[HH + h];
            float in_ = ai[r][c][2] + P.bih1[2*HH + h];
            float hr  = ah[r][c][0] + P.bhh1[h];
            float hz  = ah[r][c][1] + P.bhh1[HH + h];
            float hn  = ah[r][c][2] + P.bhh1[2*HH + h];
            float rg = sigm(ir + hr);
            float zg = sigm(iz + hz);
            float n  = tanhf(in_ + rg * hn);
            float hv = (1.0f - zg) * n + zg * hp[b*HH + h];
            g_hnew[((s*2 + 1)*BB + b)*HH + h] = hv;
            g_buf[(((s*BB + b)*TT + step)*2 + 1)*HH + h] = hv;
            g_out[((s*TT + step)*BB + b)*HH + h] = hv;
        }
    }
}

// ---------------------------------------------------------------------------
// K3: attention projections via tf32 tensor-core MMA (2xTF32 compensated).
// GEMM M=1024, N=512 (es||eh), K=256. Tile 64m x 64n, 8 warps as 2m x 4n,
// warp tile 32m x 16n = 2x2 m16n8k8 frags. Ping-pong smem + LDG prefetch.
// grid (8 n, 16 m).
// ---------------------------------------------------------------------------
__global__ __launch_bounds__(256) void k3_proj(const float* __restrict__ attn_W, int step) {
    __shared__ float As[2][64][36];   // [buf][m][k]
    __shared__ float Bs[2][32][68];   // [buf][k][n]
    const int tid = threadIdx.x;
    const int warp = tid >> 5, lane = tid & 31;
    const int gid = lane >> 2, tig = lane & 3;
    const int wm = warp & 1, wn = warp >> 1;
    const int n0 = blockIdx.x * 64, m0 = blockIdx.y * 64;
    const float* __restrict__ bsrc = (n0 < 256) ? (attn_W + n0*(2*HH))
                                                : (attn_W + (n0 - 256)*(2*HH) + HH);
    float acc[2][2][4] = {};

    const int mm = tid >> 3, kq = tid & 7;   // mm 0..31
    const float* aptr0 = &g_hnew[(m0 + mm)*HH + 4*kq];
    const float* aptr1 = &g_hnew[(m0 + mm + 32)*HH + 4*kq];
    const float* bptr0 = &bsrc[mm*(2*HH) + 4*kq];
    const float* bptr1 = &bsrc[(mm + 32)*(2*HH) + 4*kq];

    float4 pa0 = *(const float4*)aptr0;
    float4 pa1 = *(const float4*)aptr1;
    float4 pb0 = *(const float4*)bptr0;
    float4 pb1 = *(const float4*)bptr1;

    int buf = 0;
    for (int k0 = 0; k0 < HH; k0 += 32) {
        *(float4*)&As[buf][mm][4*kq]      = pa0;
        *(float4*)&As[buf][mm + 32][4*kq] = pa1;
        Bs[buf][4*kq+0][mm] = pb0.x; Bs[buf][4*kq+1][mm] = pb0.y;
        Bs[buf][4*kq+2][mm] = pb0.z; Bs[buf][4*kq+3][mm] = pb0.w;
        Bs[buf][4*kq+0][mm+32] = pb1.x; Bs[buf][4*kq+1][mm+32] = pb1.y;
        Bs[buf][4*kq+2][mm+32] = pb1.z; Bs[buf][4*kq+3][mm+32] = pb1.w;
        __syncthreads();
        if (k0 + 32 < HH) {
            pa0 = *(const float4*)(aptr0 + k0 + 32);
            pa1 = *(const float4*)(aptr1 + k0 + 32);
            pb0 = *(const float4*)(bptr0 + k0 + 32);
            pb1 = *(const float4*)(bptr1 + k0 + 32);
        }
#pragma unroll
        for (int kc = 0; kc < 32; kc += 8) {
            unsigned ah[2][4], al[2][4], bh[2][2], bl[2][2];
#pragma unroll
            for (int mf = 0; mf < 2; mf++) {
                int rb = wm*32 + mf*16;
                split_tf32(As[buf][rb + gid    ][kc + tig    ], ah[mf][0], al[mf][0]);
                split_tf32(As[buf][rb + gid + 8][kc + tig    ], ah[mf][1], al[mf][1]);
                split_tf32(As[buf][rb + gid    ][kc + tig + 4], ah[mf][2], al[mf][2]);
                split_tf32(As[buf][rb + gid + 8][kc + tig + 4], ah[mf][3], al[mf][3]);
            }
#pragma unroll
            for (int nf = 0; nf < 2; nf++) {
                int cb = wn*16 + nf*8;
                split_tf32(Bs[buf][kc + tig    ][cb + gid], bh[nf][0], bl[nf][0]);
                split_tf32(Bs[buf][kc + tig + 4][cb + gid], bh[nf][1], bl[nf][1]);
            }
#pragma unroll
            for (int mf = 0; mf < 2; mf++)
#pragma unroll
                for (int nf = 0; nf < 2; nf++) mma8(acc[mf][nf], ah[mf], bh[nf]);
#pragma unroll
            for (int mf = 0; mf < 2; mf++)
#pragma unroll
                for (int nf = 0; nf < 2; nf++) mma8(acc[mf][nf], ah[mf], bl[nf]);
#pragma unroll
            for (int mf = 0; mf < 2; mf++)
#pragma unroll
                for (int nf = 0; nf < 2; nf++) mma8(acc[mf][nf], al[mf], bh[nf]);
        }
        buf ^= 1;
    }
#pragma unroll
    for (int mf = 0; mf < 2; mf++)
#pragma unroll
        for (int nf = 0; nf < 2; nf++)
#pragma unroll
            for (int q = 0; q < 4; q++) {
                int row = m0 + wm*32 + mf*16 + gid + ((q >> 1) ? 8 : 0);
                int col = n0 + wn*16 + nf*8 + 2*tig + (q & 1);
                float v = acc[mf][nf][q];
                int s = row >> 9, l = (row >> 8) & 1, b = row & 255;
                if (n0 < 256) g_es[row*HH + col] = v;
                else g_eh[(((s*BB + b)*TT + step)*2 + l)*HH + (col - 256)] = v;
            }
}

// ---------------------------------------------------------------------------
// K4: attention energies (tanh.approx) + softmax + context (R9 version).
// ---------------------------------------------------------------------------
__global__ __launch_bounds__(256) void k4_attend(const float* __restrict__ v_W, int step) {
    const int b = blockIdx.x, s = blockIdx.y;
    const int tid = threadIdx.x, warp = tid >> 5, lane = tid & 31;
    __shared__ float lg[2][2*TT];
    __shared__ float inv[2];
    const int nrows = 2 * (step + 1);

    const int l = warp & 1;
    float esr[8], vw0[8], vw1[8];
    {
        int gb = lane * 8;
        const float* esp = g_es + ((s*2 + l)*BB + b)*HH + gb;
#pragma unroll
        for (int u = 0; u < 8; u++) {
            esr[u] = esp[u];
            vw0[u] = v_W[gb + u];
            vw1[u] = v_W[HH + gb + u];
        }
    }
    const float* ehbase = g_eh + ((s*BB + b)*TT*2) * HH;
    for (int r = warp; r < nrows; r += 8) {
        const float4* ehp = (const float4*)(ehbase + r*HH) + lane*2;
        float4 ea = ehp[0], eb = ehp[1];
        float t0 = 0.0f, t1 = 0.0f, t;
#define ESTEP(u, e) { t = tanh_fast(esr[u] + (e)); t0 += t*vw0[u]; t1 += t*vw1[u]; }
        ESTEP(0, ea.x) ESTEP(1, ea.y) ESTEP(2, ea.z) ESTEP(3, ea.w)
        ESTEP(4, eb.x) ESTEP(5, eb.y) ESTEP(6, eb.z) ESTEP(7, eb.w)
#undef ESTEP
#pragma unroll
        for (int o = 16; o; o >>= 1) {
            t0 += __shfl_xor_sync(0xffffffffu, t0, o);
            t1 += __shfl_xor_sync(0xffffffffu, t1, o);
        }
        if (lane == 0) { lg[0][r] = t0; lg[1][r] = t1; }
    }
    __syncthreads();

    if (warp < 2) {
        int o = warp;
        float m = -1e30f;
        for (int r = lane; r < nrows; r += 32) m = fmaxf(m, lg[o][r]);
#pragma unroll
        for (int off = 16; off; off >>= 1) m = fmaxf(m, __shfl_xor_sync(0xffffffffu, m, off));
        float ss = 0.0f;
        for (int r = lane; r < nrows; r += 32) {
            float e = __expf(lg[o][r] - m);
            lg[o][r] = e;
            ss += e;
        }
#pragma unroll
        for (int off = 16; off; off >>= 1) ss += __shfl_xor_sync(0xffffffffu, ss, off);
        if (lane == 0) inv[o] = 1.0f / ss;
    }
    __syncthreads();

    const float* bufbase = g_buf + ((s*BB + b)*TT*2) * HH;
    float c0 = 0.0f, c1 = 0.0f;
    int r = 0;
    for (; r + 4 <= nrows; r += 4) {
        float v0 = bufbase[(r + 0)*HH + tid];
        float v1 = bufbase[(r + 1)*HH + tid];
        float v2 = bufbase[(r + 2)*HH + tid];
        float v3 = bufbase[(r + 3)*HH + tid];
        c0 += lg[0][r]*v0 + lg[0][r+1]*v1 + lg[0][r+2]*v2 + lg[0][r+3]*v3;
        c1 += lg[1][r]*v0 + lg[1][r+1]*v1 + lg[1][r+2]*v2 + lg[1][r+3]*v3;
    }
    for (; r < nrows; r++) {
        float v = bufbase[r*HH + tid];
        c0 += lg[0][r]*v;
        c1 += lg[1][r]*v;
    }
    g_ctx[((s*2 + 0)*BB + b)*HH + tid] = c0 * inv[0];
    g_ctx[((s*2 + 1)*BB + b)*HH + tid] = c1 * inv[1];
}

// ---------------------------------------------------------------------------
// K5: fc merge via tf32 MMA (2xTF32). GEMM M=1024, N=256, K=512 (A=[ctx|hnew]).
// Tile 64m x 32n, 8 warps as 2m x 4n, warp tile 32m x 8n = 2x1 frags.
// grid (8 n, 16 m).
// ---------------------------------------------------------------------------
__global__ __launch_bounds__(256) void k5_fc(const float* __restrict__ fc_W,
                                             const float* __restrict__ fc_b) {
    __shared__ float As[2][64][36];   // [buf][m][k]
    __shared__ float Bs[2][32][36];   // [buf][k][n]
    const int tid = threadIdx.x;
    const int warp = tid >> 5, lane = tid & 31;
    const int gid = lane >> 2, tig = lane & 3;
    const int wm = warp & 1, wn = warp >> 1;
    const int n0 = blockIdx.x * 32, m0 = blockIdx.y * 64;
    float acc[2][4] = {};

    const int mm = tid >> 3, kq = tid & 7;   // mm 0..31
    const float* bptr = &fc_W[(n0 + mm)*(2*HH) + 4*kq];

    auto loadA = [&](int k0, float4& a0, float4& a1) {
        const float* Asrc = (k0 < HH) ? g_ctx : g_hnew;
        const int ko = (k0 < HH) ? k0 : (k0 - HH);
        a0 = *(const float4*)&Asrc[(m0 + mm)*HH + ko + 4*kq];
        a1 = *(const float4*)&Asrc[(m0 + mm + 32)*HH + ko + 4*kq];
    };

    float4 pa0, pa1, pb;
    loadA(0, pa0, pa1);
    pb = *(const float4*)bptr;

    int buf = 0;
    for (int k0 = 0; k0 < 2*HH; k0 += 32) {
        *(float4*)&As[buf][mm][4*kq]      = pa0;
        *(float4*)&As[buf][mm + 32][4*kq] = pa1;
        Bs[buf][4*kq+0][mm] = pb.x; Bs[buf][4*kq+1][mm] = pb.y;
        Bs[buf][4*kq+2][mm] = pb.z; Bs[buf][4*kq+3][mm] = pb.w;
        __syncthreads();
        if (k0 + 32 < 2*HH) {
            loadA(k0 + 32, pa0, pa1);
            pb = *(const float4*)(bptr + k0 + 32);
        }
#pragma unroll
        for (int kc = 0; kc < 32; kc += 8) {
            unsigned ah[2][4], al[2][4], bh[2], bl[2];
#pragma unroll
            for (int mf = 0; mf < 2; mf++) {
                int rb = wm*32 + mf*16;
                split_tf32(As[buf][rb + gid    ][kc + tig    ], ah[mf][0], al[mf][0]);
                split_tf32(As[buf][rb + gid + 8][kc + tig    ], ah[mf][1], al[mf][1]);
                split_tf32(As[buf][rb + gid    ][kc + tig + 4], ah[mf][2], al[mf][2]);
                split_tf32(As[buf][rb + gid + 8][kc + tig + 4], ah[mf][3], al[mf][3]);
            }
            {
                int cb = wn*8;
                split_tf32(Bs[buf][kc + tig    ][cb + gid], bh[0], bl[0]);
                split_tf32(Bs[buf][kc + tig + 4][cb + gid], bh[1], bl[1]);
            }
            mma8(acc[0], ah[0], bh); mma8(acc[1], ah[1], bh);
            mma8(acc[0], ah[0], bl); mma8(acc[1], ah[1], bl);
            mma8(acc[0], al[0], bh); mma8(acc[1], al[1], bh);
        }
        buf ^= 1;
    }
#pragma unroll
    for (int mf = 0; mf < 2; mf++)
#pragma unroll
        for (int q = 0; q < 4; q++) {
            int row = m0 + wm*32 + mf*16 + gid + ((q >> 1) ? 8 : 0);
            int col = n0 + wn*8 + 2*tig + (q & 1);
            g_h[row*HH + col] = acc[mf][q] + fc_b[col];
        }
}

// ---------------------------------------------------------------------------
// K6: final readout: sigmoid([out1 | delayed out2] @ out_W^T + out_b)
// ---------------------------------------------------------------------------
__global__ __launch_bounds__(256) void k6_out(const float* __restrict__ out_W,
                                              const float* __restrict__ out_b,
                                              float* __restrict__ out) {
    const int t = blockIdx.x;
    const int tid = threadIdx.x, warp = tid >> 5, lane = tid & 31;
    __shared__ float w1[HH], w2[HH];
    w1[tid] = out_W[tid];
    w2[tid] = out_W[HH + tid];
    __syncthreads();
    int t2 = (t >= TT - DD - 1) ? (TT - 1) : (t + DD);
    float ob = out_b[0];
    const float* o1b = g_out + ((0*TT + t )*BB) * HH;
    const float* o2b = g_out + ((1*TT + t2)*BB) * HH;
    for (int bb = 0; bb < 32; bb++) {
        int b = warp*32 + bb;
        const float* o1 = o1b + b*HH;
        const float* o2 = o2b + b*HH;
        float acc = 0.0f;
#pragma unroll
        for (int h = lane; h < HH; h += 32) acc += o1[h]*w1[h] + o2[h]*w2[h];
#pragma unroll
        for (int off = 16; off; off >>= 1) acc += __shfl_xor_sync(0xffffffffu, acc, off);
        if (lane == 0) out[b*TT + t] = sigm(acc + ob);
    }
}

// ---------------------------------------------------------------------------
extern "C" void kernel_launch(void* const* d_in, const int* in_sizes, int n_in,
                              void* d_out, int out_size) {
    const float* recv = (const float*)d_in[0];
    GruP p1 { (const float*)d_in[1], (const float*)d_in[2], (const float*)d_in[3], (const float*)d_in[4],
              (const float*)d_in[5], (const float*)d_in[6], (const float*)d_in[7], (const float*)d_in[8] };
    GruP p2 { (const float*)d_in[9],  (const float*)d_in[10], (const float*)d_in[11], (const float*)d_in[12],
              (const float*)d_in[13], (const float*)d_in[14], (const float*)d_in[15], (const float*)d_in[16] };
    const float* fc_W   = (const float*)d_in[17];
    const float* fc_b   = (const float*)d_in[18];
    const float* attn_W = (const float*)d_in[19];
    const float* v_W    = (const float*)d_in[20];
    const float* out_W  = (const float*)d_in[21];
    const float* out_b  = (const float*)d_in[22];
    float* out = (float*)d_out;

    k_init<<<(2*2*BB*HH + 255)/256, 256>>>();

    for (int i = 0; i < TT; i++) {
        k1_layer0<<<dim3(8, 8, 2), 256>>>(recv, p1, p2, i);
        k2_layer1<<<dim3(8, 8, 2), 256>>>(p1, p2, i);
        if (i < TT - 1) {   // attention+fc only feed the NEXT step's hidden state
            k3_proj  <<<dim3(8, 16), 256>>>(attn_W, i);
            k4_attend<<<dim3(BB, 2), 256>>>(v_W, i);
            k5_fc    <<<dim3(8, 16), 256>>>(fc_W, fc_b);
        }
    }
    k6_out<<<TT, 256>>>(out_W, out_b, out);
}

// round 17
// speedup vs baseline: 1.9231x; 1.1051x over previous
#include <cuda_runtime.h>
#include <math.h>

#define BB 256
#define TT 64
#define HH 256
#define DD 8

struct GruP {
    const float *Wih0, *Whh0, *bih0, *bhh0;
    const float *Wih1, *Whh1, *bih1, *bhh1;
};

// Persistent state (device globals: allocation-free scratch)
__device__ float g_h   [2*2*BB*HH];          // [s][l][b][h]  carried hidden
__device__ float g_hnew[2*2*BB*HH];          // [s][l][b][h]  fresh GRU hidden
__device__ float g_ctx [2*2*BB*HH];          // [s][o][b][h]  attention context
__device__ float g_es  [2*2*BB*HH];          // [s][l][b][g]  query projection
__device__ float g_buf [2*BB*TT*2*HH];       // [s][b][t][l][h]  hidden history
__device__ float g_eh  [2*BB*TT*2*HH];       // [s][b][t][l][g]  cached history proj
__device__ float g_out [2*TT*BB*HH];         // [s][t][b][h]  top-layer outputs

__device__ __forceinline__ float sigm(float x) { return 1.0f / (1.0f + __expf(-x)); }
__device__ __forceinline__ float tanh_fast(float x) {
    float y;
    asm("tanh.approx.f32 %0, %1;" : "=f"(y) : "f"(x));
    return y;
}

// ---- tf32 MMA helpers (2xTF32 compensated: hi*hi + hi*lo + lo*hi) ----
__device__ __forceinline__ unsigned cvt_tf32(float x) {
    unsigned u; asm("cvt.rna.tf32.f32 %0, %1;" : "=r"(u) : "f"(x)); return u;
}
__device__ __forceinline__ void split_tf32(float v, unsigned& hi, unsigned& lo) {
    hi = cvt_tf32(v);
    lo = cvt_tf32(v - __uint_as_float(hi));
}
__device__ __forceinline__ void mma8(float* c, const unsigned* a, const unsigned* b) {
    asm volatile("mma.sync.aligned.m16n8k8.row.col.f32.tf32.tf32.f32 "
        "{%0,%1,%2,%3}, {%4,%5,%6,%7}, {%8,%9}, {%0,%1,%2,%3};"
        : "+f"(c[0]), "+f"(c[1]), "+f"(c[2]), "+f"(c[3])
        : "r"(a[0]), "r"(a[1]), "r"(a[2]), "r"(a[3]), "r"(b[0]), "r"(b[1]));
}

__global__ void k_init() {
    int i = blockIdx.x * blockDim.x + threadIdx.x;
    if (i < 2*2*BB*HH) g_h[i] = 0.0f;
}

// ---------------------------------------------------------------------------
// K1: GRU layer 0 via tf32 MMA. gh = h_prev @ Whh0^T (3 gates) + fused gates.
// Tile 32b x 32h x 3g; 8 warps as 2m x 4n; warp frag 16m x 8n per gate.
// W stored natural [n][k] (row.col mma). grid (8 h, 8 b, 2 s).
// ---------------------------------------------------------------------------
__global__ __launch_bounds__(256) void k1_layer0(const float* __restrict__ recv,
                                                 GruP p1, GruP p2, int step) {
    const int s = blockIdx.z;
    const GruP P = s ? p2 : p1;
    __shared__ float As[32][36];        // [b][k]
    __shared__ float Ws[3][32][36];     // [g][n=h][k]
    const int tid = threadIdx.x;
    const int warp = tid >> 5, lane = tid & 31;
    const int gid = lane >> 2, tig = lane & 3;
    const int wm = warp & 1, wn = warp >> 1;
    const int b0 = blockIdx.y * 32, hc0 = blockIdx.x * 32;
    const float* __restrict__ hprev = g_h + s * 2 * BB * HH;
    float acc[3][4] = {};

    const int mm = tid >> 3, kq = tid & 7;
    const float* aptr = &hprev[(b0 + mm)*HH + 4*kq];
    const float* wptr = &P.Whh0[(hc0 + mm)*HH + 4*kq];

    float4 pa  = *(const float4*)aptr;
    float4 pw0 = *(const float4*)(wptr);
    float4 pw1 = *(const float4*)(wptr + HH*HH);
    float4 pw2 = *(const float4*)(wptr + 2*HH*HH);

    for (int k0 = 0; k0 < HH; k0 += 32) {
        *(float4*)&As[mm][4*kq]    = pa;
        *(float4*)&Ws[0][mm][4*kq] = pw0;
        *(float4*)&Ws[1][mm][4*kq] = pw1;
        *(float4*)&Ws[2][mm][4*kq] = pw2;
        __syncthreads();
        if (k0 + 32 < HH) {
            pa  = *(const float4*)(aptr + k0 + 32);
            pw0 = *(const float4*)(wptr + k0 + 32);
            pw1 = *(const float4*)(wptr + HH*HH + k0 + 32);
            pw2 = *(const float4*)(wptr + 2*HH*HH + k0 + 32);
        }
#pragma unroll
        for (int kc = 0; kc < 32; kc += 8) {
            unsigned ah[4], al[4];
            split_tf32(As[wm*16 + gid    ][kc + tig    ], ah[0], al[0]);
            split_tf32(As[wm*16 + gid + 8][kc + tig    ], ah[1], al[1]);
            split_tf32(As[wm*16 + gid    ][kc + tig + 4], ah[2], al[2]);
            split_tf32(As[wm*16 + gid + 8][kc + tig + 4], ah[3], al[3]);
#pragma unroll
            for (int g = 0; g < 3; g++) {
                unsigned bh[2], bl[2];
                split_tf32(Ws[g][wn*8 + gid][kc + tig    ], bh[0], bl[0]);
                split_tf32(Ws[g][wn*8 + gid][kc + tig + 4], bh[1], bl[1]);
                mma8(acc[g], ah, bh);
                mma8(acc[g], ah, bl);
                mma8(acc[g], al, bh);
            }
        }
        __syncthreads();
    }
#pragma unroll
    for (int q = 0; q < 4; q++) {
        int b = b0 + wm*16 + gid + ((q >> 1) ? 8 : 0);
        int h = hc0 + wn*8 + 2*tig + (q & 1);
        float x0 = recv[(b*TT + step)*2 + 0];
        float x1 = recv[(b*TT + step)*2 + 1];
        float ir  = P.Wih0[h*2]          * x0 + P.Wih0[h*2 + 1]          * x1 + P.bih0[h];
        float iz  = P.Wih0[(HH + h)*2]   * x0 + P.Wih0[(HH + h)*2 + 1]   * x1 + P.bih0[HH + h];
        float in_ = P.Wih0[(2*HH + h)*2] * x0 + P.Wih0[(2*HH + h)*2 + 1] * x1 + P.bih0[2*HH + h];
        float hr = acc[0][q] + P.bhh0[h];
        float hz = acc[1][q] + P.bhh0[HH + h];
        float hn = acc[2][q] + P.bhh0[2*HH + h];
        float rg = sigm(ir + hr);
        float zg = sigm(iz + hz);
        float n  = tanhf(in_ + rg * hn);
        float hv = (1.0f - zg) * n + zg * hprev[b*HH + h];
        g_hnew[((s*2 + 0)*BB + b)*HH + h] = hv;
        g_buf[(((s*BB + b)*TT + step)*2 + 0)*HH + h] = hv;
    }
}

// ---------------------------------------------------------------------------
// K2: GRU layer 1 via tf32 MMA. Two GEMMs (hnew0@Wih1, h1@Whh1), 3 gates each,
// fused gate epilogue. Same tiling as K1. grid (8 h, 8 b, 2 s).
// ---------------------------------------------------------------------------
__global__ __launch_bounds__(256) void k2_layer1(GruP p1, GruP p2, int step) {
    const int s = blockIdx.z;
    const GruP P = s ? p2 : p1;
    __shared__ float A1s[32][36], A2s[32][36];
    __shared__ float Wi[3][32][36], Wh[3][32][36];
    const int tid = threadIdx.x;
    const int warp = tid >> 5, lane = tid & 31;
    const int gid = lane >> 2, tig = lane & 3;
    const int wm = warp & 1, wn = warp >> 1;
    const int b0 = blockIdx.y * 32, hc0 = blockIdx.x * 32;
    const float* __restrict__ xin = g_hnew + (s*2 + 0) * BB * HH;
    const float* __restrict__ hp  = g_h    + (s*2 + 1) * BB * HH;
    float ai[3][4] = {}, ah_[3][4] = {};

    const int mm = tid >> 3, kq = tid & 7;
    const float* a1ptr = &xin[(b0 + mm)*HH + 4*kq];
    const float* a2ptr = &hp [(b0 + mm)*HH + 4*kq];
    const float* wiptr = &P.Wih1[(hc0 + mm)*HH + 4*kq];
    const float* whptr = &P.Whh1[(hc0 + mm)*HH + 4*kq];

    float4 pa1 = *(const float4*)a1ptr;
    float4 pa2 = *(const float4*)a2ptr;
    float4 pi0 = *(const float4*)(wiptr);
    float4 pi1 = *(const float4*)(wiptr + HH*HH);
    float4 pi2 = *(const float4*)(wiptr + 2*HH*HH);
    float4 ph0 = *(const float4*)(whptr);
    float4 ph1 = *(const float4*)(whptr + HH*HH);
    float4 ph2 = *(const float4*)(whptr + 2*HH*HH);

    for (int k0 = 0; k0 < HH; k0 += 32) {
        *(float4*)&A1s[mm][4*kq]   = pa1;
        *(float4*)&A2s[mm][4*kq]   = pa2;
        *(float4*)&Wi[0][mm][4*kq] = pi0;
        *(float4*)&Wi[1][mm][4*kq] = pi1;
        *(float4*)&Wi[2][mm][4*kq] = pi2;
        *(float4*)&Wh[0][mm][4*kq] = ph0;
        *(float4*)&Wh[1][mm][4*kq] = ph1;
        *(float4*)&Wh[2][mm][4*kq] = ph2;
        __syncthreads();
        if (k0 + 32 < HH) {
            pa1 = *(const float4*)(a1ptr + k0 + 32);
            pa2 = *(const float4*)(a2ptr + k0 + 32);
            pi0 = *(const float4*)(wiptr + k0 + 32);
            pi1 = *(const float4*)(wiptr + HH*HH + k0 + 32);
            pi2 = *(const float4*)(wiptr + 2*HH*HH + k0 + 32);
            ph0 = *(const float4*)(whptr + k0 + 32);
            ph1 = *(const float4*)(whptr + HH*HH + k0 + 32);
            ph2 = *(const float4*)(whptr + 2*HH*HH + k0 + 32);
        }
#pragma unroll
        for (int kc = 0; kc < 32; kc += 8) {
            unsigned a1h[4], a1l[4], a2h[4], a2l[4];
            split_tf32(A1s[wm*16 + gid    ][kc + tig    ], a1h[0], a1l[0]);
            split_tf32(A1s[wm*16 + gid + 8][kc + tig    ], a1h[1], a1l[1]);
            split_tf32(A1s[wm*16 + gid    ][kc + tig + 4], a1h[2], a1l[2]);
            split_tf32(A1s[wm*16 + gid + 8][kc + tig + 4], a1h[3], a1l[3]);
            split_tf32(A2s[wm*16 + gid    ][kc + tig    ], a2h[0], a2l[0]);
            split_tf32(A2s[wm*16 + gid + 8][kc + tig    ], a2h[1], a2l[1]);
            split_tf32(A2s[wm*16 + gid    ][kc + tig + 4], a2h[2], a2l[2]);
            split_tf32(A2s[wm*16 + gid + 8][kc + tig + 4], a2h[3], a2l[3]);
#pragma unroll
            for (int g = 0; g < 3; g++) {
                unsigned bh[2], bl[2];
                split_tf32(Wi[g][wn*8 + gid][kc + tig    ], bh[0], bl[0]);
                split_tf32(Wi[g][wn*8 + gid][kc + tig + 4], bh[1], bl[1]);
                mma8(ai[g], a1h, bh);
                mma8(ai[g], a1h, bl);
                mma8(ai[g], a1l, bh);
                split_tf32(Wh[g][wn*8 + gid][kc + tig    ], bh[0], bl[0]);
                split_tf32(Wh[g][wn*8 + gid][kc + tig + 4], bh[1], bl[1]);
                mma8(ah_[g], a2h, bh);
                mma8(ah_[g], a2h, bl);
                mma8(ah_[g], a2l, bh);
            }
        }
        __syncthreads();
    }
#pragma unroll
    for (int q = 0; q < 4; q++) {
        int b = b0 + wm*16 + gid + ((q >> 1) ? 8 : 0);
        int h = hc0 + wn*8 + 2*tig + (q & 1);
        float ir  = ai[0][q] + P.bih1[h];
        float iz  = ai[1][q] + P.bih1[HH + h];
        float in_ = ai[2][q] + P.bih1[2*HH + h];
        float hr  = ah_[0][q] + P.bhh1[h];
        float hz  = ah_[1][q] + P.bhh1[HH + h];
        float hn  = ah_[2][q] + P.bhh1[2*HH + h];
        float rg = sigm(ir + hr);
        float zg = sigm(iz + hz);
        float n  = tanhf(in_ + rg * hn);
        float hv = (1.0f - zg) * n + zg * hp[b*HH + h];
        g_hnew[((s*2 + 1)*BB + b)*HH + h] = hv;
        g_buf[(((s*BB + b)*TT + step)*2 + 1)*HH + h] = hv;
        g_out[((s*TT + step)*BB + b)*HH + h] = hv;
    }
}

// ---------------------------------------------------------------------------
// K3: attention projections via tf32 MMA (2xTF32 compensated). R16 version.
// ---------------------------------------------------------------------------
__global__ __launch_bounds__(256) void k3_proj(const float* __restrict__ attn_W, int step) {
    __shared__ float As[2][64][36];   // [buf][m][k]
    __shared__ float Bs[2][32][68];   // [buf][k][n]
    const int tid = threadIdx.x;
    const int warp = tid >> 5, lane = tid & 31;
    const int gid = lane >> 2, tig = lane & 3;
    const int wm = warp & 1, wn = warp >> 1;
    const int n0 = blockIdx.x * 64, m0 = blockIdx.y * 64;
    const float* __restrict__ bsrc = (n0 < 256) ? (attn_W + n0*(2*HH))
                                                : (attn_W + (n0 - 256)*(2*HH) + HH);
    float acc[2][2][4] = {};

    const int mm = tid >> 3, kq = tid & 7;   // mm 0..31
    const float* aptr0 = &g_hnew[(m0 + mm)*HH + 4*kq];
    const float* aptr1 = &g_hnew[(m0 + mm + 32)*HH + 4*kq];
    const float* bptr0 = &bsrc[mm*(2*HH) + 4*kq];
    const float* bptr1 = &bsrc[(mm + 32)*(2*HH) + 4*kq];

    float4 pa0 = *(const float4*)aptr0;
    float4 pa1 = *(const float4*)aptr1;
    float4 pb0 = *(const float4*)bptr0;
    float4 pb1 = *(const float4*)bptr1;

    int buf = 0;
    for (int k0 = 0; k0 < HH; k0 += 32) {
        *(float4*)&As[buf][mm][4*kq]      = pa0;
        *(float4*)&As[buf][mm + 32][4*kq] = pa1;
        Bs[buf][4*kq+0][mm] = pb0.x; Bs[buf][4*kq+1][mm] = pb0.y;
        Bs[buf][4*kq+2][mm] = pb0.z; Bs[buf][4*kq+3][mm] = pb0.w;
        Bs[buf][4*kq+0][mm+32] = pb1.x; Bs[buf][4*kq+1][mm+32] = pb1.y;
        Bs[buf][4*kq+2][mm+32] = pb1.z; Bs[buf][4*kq+3][mm+32] = pb1.w;
        __syncthreads();
        if (k0 + 32 < HH) {
            pa0 = *(const float4*)(aptr0 + k0 + 32);
            pa1 = *(const float4*)(aptr1 + k0 + 32);
            pb0 = *(const float4*)(bptr0 + k0 + 32);
            pb1 = *(const float4*)(bptr1 + k0 + 32);
        }
#pragma unroll
        for (int kc = 0; kc < 32; kc += 8) {
            unsigned ah[2][4], al[2][4], bh[2][2], bl[2][2];
#pragma unroll
            for (int mf = 0; mf < 2; mf++) {
                int rb = wm*32 + mf*16;
                split_tf32(As[buf][rb + gid    ][kc + tig    ], ah[mf][0], al[mf][0]);
                split_tf32(As[buf][rb + gid + 8][kc + tig    ], ah[mf][1], al[mf][1]);
                split_tf32(As[buf][rb + gid    ][kc + tig + 4], ah[mf][2], al[mf][2]);
                split_tf32(As[buf][rb + gid + 8][kc + tig + 4], ah[mf][3], al[mf][3]);
            }
#pragma unroll
            for (int nf = 0; nf < 2; nf++) {
                int cb = wn*16 + nf*8;
                split_tf32(Bs[buf][kc + tig    ][cb + gid], bh[nf][0], bl[nf][0]);
                split_tf32(Bs[buf][kc + tig + 4][cb + gid], bh[nf][1], bl[nf][1]);
            }
#pragma unroll
            for (int mf = 0; mf < 2; mf++)
#pragma unroll
                for (int nf = 0; nf < 2; nf++) mma8(acc[mf][nf], ah[mf], bh[nf]);
#pragma unroll
            for (int mf = 0; mf < 2; mf++)
#pragma unroll
                for (int nf = 0; nf < 2; nf++) mma8(acc[mf][nf], ah[mf], bl[nf]);
#pragma unroll
            for (int mf = 0; mf < 2; mf++)
#pragma unroll
                for (int nf = 0; nf < 2; nf++) mma8(acc[mf][nf], al[mf], bh[nf]);
        }
        buf ^= 1;
    }
#pragma unroll
    for (int mf = 0; mf < 2; mf++)
#pragma unroll
        for (int nf = 0; nf < 2; nf++)
#pragma unroll
            for (int q = 0; q < 4; q++) {
                int row = m0 + wm*32 + mf*16 + gid + ((q >> 1) ? 8 : 0);
                int col = n0 + wn*16 + nf*8 + 2*tig + (q & 1);
                float v = acc[mf][nf][q];
                int s = row >> 9, l = (row >> 8) & 1, b = row & 255;
                if (n0 < 256) g_es[row*HH + col] = v;
                else g_eh[(((s*BB + b)*TT + step)*2 + l)*HH + (col - 256)] = v;
            }
}

// ---------------------------------------------------------------------------
// K4: attention energies (tanh.approx) + softmax + context (R9 version).
// ---------------------------------------------------------------------------
__global__ __launch_bounds__(256) void k4_attend(const float* __restrict__ v_W, int step) {
    const int b = blockIdx.x, s = blockIdx.y;
    const int tid = threadIdx.x, warp = tid >> 5, lane = tid & 31;
    __shared__ float lg[2][2*TT];
    __shared__ float inv[2];
    const int nrows = 2 * (step + 1);

    const int l = warp & 1;
    float esr[8], vw0[8], vw1[8];
    {
        int gb = lane * 8;
        const float* esp = g_es + ((s*2 + l)*BB + b)*HH + gb;
#pragma unroll
        for (int u = 0; u < 8; u++) {
            esr[u] = esp[u];
            vw0[u] = v_W[gb + u];
            vw1[u] = v_W[HH + gb + u];
        }
    }
    const float* ehbase = g_eh + ((s*BB + b)*TT*2) * HH;
    for (int r = warp; r < nrows; r += 8) {
        const float4* ehp = (const float4*)(ehbase + r*HH) + lane*2;
        float4 ea = ehp[0], eb = ehp[1];
        float t0 = 0.0f, t1 = 0.0f, t;
#define ESTEP(u, e) { t = tanh_fast(esr[u] + (e)); t0 += t*vw0[u]; t1 += t*vw1[u]; }
        ESTEP(0, ea.x) ESTEP(1, ea.y) ESTEP(2, ea.z) ESTEP(3, ea.w)
        ESTEP(4, eb.x) ESTEP(5, eb.y) ESTEP(6, eb.z) ESTEP(7, eb.w)
#undef ESTEP
#pragma unroll
        for (int o = 16; o; o >>= 1) {
            t0 += __shfl_xor_sync(0xffffffffu, t0, o);
            t1 += __shfl_xor_sync(0xffffffffu, t1, o);
        }
        if (lane == 0) { lg[0][r] = t0; lg[1][r] = t1; }
    }
    __syncthreads();

    if (warp < 2) {
        int o = warp;
        float m = -1e30f;
        for (int r = lane; r < nrows; r += 32) m = fmaxf(m, lg[o][r]);
#pragma unroll
        for (int off = 16; off; off >>= 1) m = fmaxf(m, __shfl_xor_sync(0xffffffffu, m, off));
        float ss = 0.0f;
        for (int r = lane; r < nrows; r += 32) {
            float e = __expf(lg[o][r] - m);
            lg[o][r] = e;
            ss += e;
        }
#pragma unroll
        for (int off = 16; off; off >>= 1) ss += __shfl_xor_sync(0xffffffffu, ss, off);
        if (lane == 0) inv[o] = 1.0f / ss;
    }
    __syncthreads();

    const float* bufbase = g_buf + ((s*BB + b)*TT*2) * HH;
    float c0 = 0.0f, c1 = 0.0f;
    int r = 0;
    for (; r + 4 <= nrows; r += 4) {
        float v0 = bufbase[(r + 0)*HH + tid];
        float v1 = bufbase[(r + 1)*HH + tid];
        float v2 = bufbase[(r + 2)*HH + tid];
        float v3 = bufbase[(r + 3)*HH + tid];
        c0 += lg[0][r]*v0 + lg[0][r+1]*v1 + lg[0][r+2]*v2 + lg[0][r+3]*v3;
        c1 += lg[1][r]*v0 + lg[1][r+1]*v1 + lg[1][r+2]*v2 + lg[1][r+3]*v3;
    }
    for (; r < nrows; r++) {
        float v = bufbase[r*HH + tid];
        c0 += lg[0][r]*v;
        c1 += lg[1][r]*v;
    }
    g_ctx[((s*2 + 0)*BB + b)*HH + tid] = c0 * inv[0];
    g_ctx[((s*2 + 1)*BB + b)*HH + tid] = c1 * inv[1];
}

// ---------------------------------------------------------------------------
// K5: fc merge via tf32 MMA (2xTF32). R16 version.
// ---------------------------------------------------------------------------
__global__ __launch_bounds__(256) void k5_fc(const float* __restrict__ fc_W,
                                             const float* __restrict__ fc_b) {
    __shared__ float As[2][64][36];   // [buf][m][k]
    __shared__ float Bs[2][32][36];   // [buf][k][n]
    const int tid = threadIdx.x;
    const int warp = tid >> 5, lane = tid & 31;
    const int gid = lane >> 2, tig = lane & 3;
    const int wm = warp & 1, wn = warp >> 1;
    const int n0 = blockIdx.x * 32, m0 = blockIdx.y * 64;
    float acc[2][4] = {};

    const int mm = tid >> 3, kq = tid & 7;   // mm 0..31
    const float* bptr = &fc_W[(n0 + mm)*(2*HH) + 4*kq];

    auto loadA = [&](int k0, float4& a0, float4& a1) {
        const float* Asrc = (k0 < HH) ? g_ctx : g_hnew;
        const int ko = (k0 < HH) ? k0 : (k0 - HH);
        a0 = *(const float4*)&Asrc[(m0 + mm)*HH + ko + 4*kq];
        a1 = *(const float4*)&Asrc[(m0 + mm + 32)*HH + ko + 4*kq];
    };

    float4 pa0, pa1, pb;
    loadA(0, pa0, pa1);
    pb = *(const float4*)bptr;

    int buf = 0;
    for (int k0 = 0; k0 < 2*HH; k0 += 32) {
        *(float4*)&As[buf][mm][4*kq]      = pa0;
        *(float4*)&As[buf][mm + 32][4*kq] = pa1;
        Bs[buf][4*kq+0][mm] = pb.x; Bs[buf][4*kq+1][mm] = pb.y;
        Bs[buf][4*kq+2][mm] = pb.z; Bs[buf][4*kq+3][mm] = pb.w;
        __syncthreads();
        if (k0 + 32 < 2*HH) {
            loadA(k0 + 32, pa0, pa1);
            pb = *(const float4*)(bptr + k0 + 32);
        }
#pragma unroll
        for (int kc = 0; kc < 32; kc += 8) {
            unsigned ah[2][4], al[2][4], bh[2], bl[2];
#pragma unroll
            for (int mf = 0; mf < 2; mf++) {
                int rb = wm*32 + mf*16;
                split_tf32(As[buf][rb + gid    ][kc + tig    ], ah[mf][0], al[mf][0]);
                split_tf32(As[buf][rb + gid + 8][kc + tig    ], ah[mf][1], al[mf][1]);
                split_tf32(As[buf][rb + gid    ][kc + tig + 4], ah[mf][2], al[mf][2]);
                split_tf32(As[buf][rb + gid + 8][kc + tig + 4], ah[mf][3], al[mf][3]);
            }
            {
                int cb = wn*8;
                split_tf32(Bs[buf][kc + tig    ][cb + gid], bh[0], bl[0]);
                split_tf32(Bs[buf][kc + tig + 4][cb + gid], bh[1], bl[1]);
            }
            mma8(acc[0], ah[0], bh); mma8(acc[1], ah[1], bh);
            mma8(acc[0], ah[0], bl); mma8(acc[1], ah[1], bl);
            mma8(acc[0], al[0], bh); mma8(acc[1], al[1], bh);
        }
        buf ^= 1;
    }
#pragma unroll
    for (int mf = 0; mf < 2; mf++)
#pragma unroll
        for (int q = 0; q < 4; q++) {
            int row = m0 + wm*32 + mf*16 + gid + ((q >> 1) ? 8 : 0);
            int col = n0 + wn*8 + 2*tig + (q & 1);
            g_h[row*HH + col] = acc[mf][q] + fc_b[col];
        }
}

// ---------------------------------------------------------------------------
// K6: final readout: sigmoid([out1 | delayed out2] @ out_W^T + out_b)
// ---------------------------------------------------------------------------
__global__ __launch_bounds__(256) void k6_out(const float* __restrict__ out_W,
                                              const float* __restrict__ out_b,
                                              float* __restrict__ out) {
    const int t = blockIdx.x;
    const int tid = threadIdx.x, warp = tid >> 5, lane = tid & 31;
    __shared__ float w1[HH], w2[HH];
    w1[tid] = out_W[tid];
    w2[tid] = out_W[HH + tid];
    __syncthreads();
    int t2 = (t >= TT - DD - 1) ? (TT - 1) : (t + DD);
    float ob = out_b[0];
    const float* o1b = g_out + ((0*TT + t )*BB) * HH;
    const float* o2b = g_out + ((1*TT + t2)*BB) * HH;
    for (int bb = 0; bb < 32; bb++) {
        int b = warp*32 + bb;
        const float* o1 = o1b + b*HH;
        const float* o2 = o2b + b*HH;
        float acc = 0.0f;
#pragma unroll
        for (int h = lane; h < HH; h += 32) acc += o1[h]*w1[h] + o2[h]*w2[h];
#pragma unroll
        for (int off = 16; off; off >>= 1) acc += __shfl_xor_sync(0xffffffffu, acc, off);
        if (lane == 0) out[b*TT + t] = sigm(acc + ob);
    }
}

// ---------------------------------------------------------------------------
extern "C" void kernel_launch(void* const* d_in, const int* in_sizes, int n_in,
                              void* d_out, int out_size) {
    const float* recv = (const float*)d_in[0];
    GruP p1 { (const float*)d_in[1], (const float*)d_in[2], (const float*)d_in[3], (const float*)d_in[4],
              (const float*)d_in[5], (const float*)d_in[6], (const float*)d_in[7], (const float*)d_in[8] };
    GruP p2 { (const float*)d_in[9],  (const float*)d_in[10], (const float*)d_in[11], (const float*)d_in[12],
              (const float*)d_in[13], (const float*)d_in[14], (const float*)d_in[15], (const float*)d_in[16] };
    const float* fc_W   = (const float*)d_in[17];
    const float* fc_b   = (const float*)d_in[18];
    const float* attn_W = (const float*)d_in[19];
    const float* v_W    = (const float*)d_in[20];
    const float* out_W  = (const float*)d_in[21];
    const float* out_b  = (const float*)d_in[22];
    float* out = (float*)d_out;

    k_init<<<(2*2*BB*HH + 255)/256, 256>>>();

    for (int i = 0; i < TT; i++) {
        k1_layer0<<<dim3(8, 8, 2), 256>>>(recv, p1, p2, i);
        k2_layer1<<<dim3(8, 8, 2), 256>>>(p1, p2, i);
        if (i < TT - 1) {   // attention+fc only feed the NEXT step's hidden state
            k3_proj  <<<dim3(8, 16), 256>>>(attn_W, i);
            k4_attend<<<dim3(BB, 2), 256>>>(v_W, i);
            k5_fc    <<<dim3(8, 16), 256>>>(fc_W, fc_b);
        }
    }
    k6_out<<<TT, 256>>>(out_W, out_b, out);
}